// round 13
// baseline (speedup 1.0000x reference)
#include <cuda_runtime.h>
#include <cuda_bf16.h>
#include <math.h>
#include <stdint.h>

// ---------------------------------------------------------------------------
// Problem constants
// ---------------------------------------------------------------------------
#define NCAND 100000
#define BQ    1024
#define NT    (NCAND + BQ)
#define DM    256
#define DH    512
#define NNUM  96
#define MCTX  96
#define RN    (BQ * MCTX)

typedef __nv_bfloat16 bf16;

// ---------------------------------------------------------------------------
// Device scratch
// ---------------------------------------------------------------------------
__device__ float g_U    [(size_t)RN * DM];
__device__ float g_score[(size_t)BQ * NCAND];
__device__ float g_hnneg[NCAND];
__device__ float g_px [BQ * DM];
__device__ int   g_idx [BQ * MCTX];
__device__ float g_probs[BQ * MCTX];

__device__ bf16 g_xh [(size_t)NT * 96],  g_xl [(size_t)NT * 96];
__device__ bf16 g_h0h[(size_t)NT * DM],  g_h0l[(size_t)NT * DM];
__device__ bf16 g_th [(size_t)NT * DH],  g_tl [(size_t)NT * DH];
__device__ bf16 g_lnh[(size_t)NT * DM],  g_lnl[(size_t)NT * DM];
__device__ bf16 g_ckh[(size_t)NT * DM],  g_ckl[(size_t)NT * DM];
__device__ bf16 g_dh [(size_t)RN * DM],  g_dl [(size_t)RN * DM];
__device__ bf16 g_t2h[(size_t)RN * DH],  g_t2l[(size_t)RN * DH];
__device__ bf16 g_pxh[BQ * DM], g_pxl[BQ * DM];
__device__ bf16 g_pth[BQ * DH], g_ptl[BQ * DH];

__device__ bf16 g_winh[256 * 96],  g_winl[256 * 96];
__device__ bf16 g_we1h[512 * 256], g_we1l[512 * 256];
__device__ bf16 g_we2h[256 * 512], g_we2l[256 * 512];
__device__ bf16 g_wsh [256 * 256], g_wsl [256 * 256];
__device__ bf16 g_wt1h[512 * 256], g_wt1l[512 * 256];
__device__ bf16 g_wt2h[256 * 512], g_wt2l[256 * 512];
__device__ bf16 g_wp1h[512 * 256], g_wp1l[512 * 256];
__device__ bf16 g_wp2h[256 * 512], g_wp2l[256 * 512];

// ---------------------------------------------------------------------------
// Helpers
// ---------------------------------------------------------------------------
__device__ __forceinline__ uint32_t smem_u32(const void* p) {
    uint32_t a;
    asm("{ .reg .u64 t; cvta.to.shared.u64 t, %1; cvt.u32.u64 %0, t; }" : "=r"(a) : "l"(p));
    return a;
}

__device__ __forceinline__ void cp16(uint32_t dst, const void* src, bool valid) {
    int sz = valid ? 16 : 0;
    asm volatile("cp.async.cg.shared.global [%0], [%1], 16, %2;"
                 :: "r"(dst), "l"(src), "r"(sz));
}
#define CP_COMMIT() asm volatile("cp.async.commit_group;")
#define CP_WAIT(n)  asm volatile("cp.async.wait_group %0;" :: "n"(n))

__device__ __forceinline__ void ldsm4(uint32_t addr, uint32_t& r0, uint32_t& r1,
                                      uint32_t& r2, uint32_t& r3) {
    asm volatile("ldmatrix.sync.aligned.m8n8.x4.shared.b16 {%0,%1,%2,%3}, [%4];"
                 : "=r"(r0), "=r"(r1), "=r"(r2), "=r"(r3) : "r"(addr));
}

__device__ __forceinline__ void mma16816(float* c, const uint32_t* a, const uint32_t* b) {
    asm volatile(
        "mma.sync.aligned.m16n8k16.row.col.f32.bf16.bf16.f32 "
        "{%0,%1,%2,%3}, {%4,%5,%6,%7}, {%8,%9}, {%0,%1,%2,%3};"
        : "+f"(c[0]), "+f"(c[1]), "+f"(c[2]), "+f"(c[3])
        : "r"(a[0]), "r"(a[1]), "r"(a[2]), "r"(a[3]), "r"(b[0]), "r"(b[1]));
}

__device__ __forceinline__ float block_sum_256(float v) {
    __shared__ float sh[8];
    int lane = threadIdx.x & 31, w = threadIdx.x >> 5;
    #pragma unroll
    for (int o = 16; o > 0; o >>= 1) v += __shfl_xor_sync(0xffffffffu, v, o);
    __syncthreads();
    if (lane == 0) sh[w] = v;
    __syncthreads();
    float t = sh[0];
    #pragma unroll
    for (int i = 1; i < 8; i++) t += sh[i];
    return t;
}

__device__ __forceinline__ float warp_sum(float v) {
    #pragma unroll
    for (int o = 16; o > 0; o >>= 1) v += __shfl_xor_sync(0xffffffffu, v, o);
    return v;
}

__device__ __forceinline__ void split2(float v, bf16& h, bf16& l) {
    h = __float2bfloat16(v);
    l = __float2bfloat16(v - __bfloat162float(h));
}

// ---------------------------------------------------------------------------
// gemm_mma: FROZEN round-10/12 core.
// flags: 1 relu, 2 +res(f32), 4 write f32 C, 8 write split (Ch,Cl),
//        16 +res split (Rh+Rl), 32 swap block-index mapping, 64 two-segment
// ---------------------------------------------------------------------------
#define LDA 40
#define STG_ELEM (128 * LDA)
#define STAGE_BYTES (2 * STG_ELEM * 2)
#define NSTAGE 5
#define GEMM_SMEM (NSTAGE * STAGE_BYTES)

__global__ __launch_bounds__(256, 2)
void gemm_mma(const bf16* __restrict__ Ah, const bf16* __restrict__ Al,
              const bf16* __restrict__ Bh, const bf16* __restrict__ Bl,
              const float* __restrict__ bias, const float* __restrict__ res,
              const bf16* __restrict__ Rh, const bf16* __restrict__ Rl,
              float* __restrict__ C, bf16* __restrict__ Ch, bf16* __restrict__ Cl,
              int M, int N, int Kp, int flags)
{
    extern __shared__ __align__(16) bf16 sdyn[];
    __shared__ float sbias[128];

    const int tid  = threadIdx.x;
    const int lane = tid & 31;
    const int wid  = tid >> 5;
    const int wm   = wid & 3;
    const int wn   = wid >> 2;
    const int bm   = ((flags & 32) ? blockIdx.x : blockIdx.y) * 128;
    const int bn   = ((flags & 32) ? blockIdx.y : blockIdx.x) * 128;

    if (tid < 128) {
        int col = bn + tid;
        sbias[tid] = (bias != nullptr && col < N) ? bias[col] : 0.f;
    }

    const uint32_t sBase = smem_u32(sdyn);

    const bf16* segA[3] = {Ah, Ah, Al};
    const bf16* segB[3] = {Bh, Bl, Bh};
    if (flags & 64) { segA[1] = Al; segB[1] = Bh; }
    const int nseg = (flags & 64) ? 2 : 3;
    const int nk = Kp >> 5;
    const int NC = nseg * nk;

    float acc[2][8][4];
    #pragma unroll
    for (int t = 0; t < 2; t++)
        #pragma unroll
        for (int j = 0; j < 8; j++)
            #pragma unroll
            for (int e = 0; e < 4; e++) acc[t][j][e] = 0.f;

    auto issue = [&](int c, int st) {
        int seg = c / nk;
        int k0  = (c - seg * nk) << 5;
        const bf16* Ap = segA[seg];
        const bf16* Bp = segB[seg];
        uint32_t stA = sBase + (uint32_t)(st * STAGE_BYTES);
        uint32_t stB = stA + STG_ELEM * 2;
        #pragma unroll
        for (int h = 0; h < 2; h++) {
            int q   = tid + h * 256;
            int row = q >> 2;
            int sg  = q & 3;
            uint32_t off = (uint32_t)(row * 80 + sg * 16);
            int ar = bm + row; bool av = ar < M; if (!av) ar = 0;
            cp16(stA + off, Ap + (size_t)ar * Kp + k0 + sg * 8, av);
            int br = bn + row; bool bv = br < N; if (!bv) br = 0;
            cp16(stB + off, Bp + (size_t)br * Kp + k0 + sg * 8, bv);
        }
        CP_COMMIT();
    };

    issue(0, 0);
    issue(1, 1);
    issue(2, 2);
    int st_w = 3, st_r = 0;
    for (int c = 0; c < NC; ++c) {
        if (c + 3 < NC) {
            issue(c + 3, st_w);
            if (++st_w == NSTAGE) st_w = 0;
        } else {
            CP_COMMIT();
        }
        CP_WAIT(3);
        __syncthreads();

        uint32_t stA = sBase + (uint32_t)(st_r * STAGE_BYTES);
        uint32_t stB = stA + STG_ELEM * 2;
        if (++st_r == NSTAGE) st_r = 0;
        uint32_t aBase = stA + (uint32_t)((wm * 32) * 80);
        uint32_t bBase = stB + (uint32_t)((wn * 64) * 80);

        #pragma unroll
        for (int ks = 0; ks < 32; ks += 16) {
            uint32_t a[2][4];
            #pragma unroll
            for (int t = 0; t < 2; t++) {
                uint32_t addr = aBase + (uint32_t)((t * 16 + (lane & 15)) * 80
                                                   + (ks + (lane >> 4) * 8) * 2);
                ldsm4(addr, a[t][0], a[t][1], a[t][2], a[t][3]);
            }
            uint32_t b[8][2];
            #pragma unroll
            for (int jp = 0; jp < 4; jp++) {
                int grp = lane >> 3;
                int row = jp * 16 + (grp >> 1) * 8 + (lane & 7);
                int kof = (grp & 1) * 8;
                uint32_t addr = bBase + (uint32_t)(row * 80 + (ks + kof) * 2);
                ldsm4(addr, b[2 * jp][0], b[2 * jp][1], b[2 * jp + 1][0], b[2 * jp + 1][1]);
            }
            #pragma unroll
            for (int t = 0; t < 2; t++)
                #pragma unroll
                for (int j = 0; j < 8; j++)
                    mma16816(acc[t][j], a[t], b[j]);
        }
    }

    // ---- epilogue ----
    int colb = (lane & 3) * 2;
    #pragma unroll
    for (int t = 0; t < 2; t++) {
        int row0 = bm + wm * 32 + t * 16 + (lane >> 2);
        #pragma unroll
        for (int j = 0; j < 8; j++) {
            int col = bn + wn * 64 + j * 8 + colb;
            if (col >= N) continue;
            #pragma unroll
            for (int half = 0; half < 2; half++) {
                int rr = row0 + half * 8;
                if (rr >= M) continue;
                float v0 = acc[t][j][half * 2 + 0];
                float v1 = acc[t][j][half * 2 + 1];
                int cl = col - bn;
                v0 += sbias[cl]; v1 += sbias[cl + 1];
                if (flags & 1) { v0 = fmaxf(v0, 0.f); v1 = fmaxf(v1, 0.f); }
                size_t o = (size_t)rr * N + col;
                if (flags & 2) {
                    float2 r2 = *reinterpret_cast<const float2*>(res + o);
                    v0 += r2.x; v1 += r2.y;
                }
                if (flags & 16) {
                    __nv_bfloat162 rh = *reinterpret_cast<const __nv_bfloat162*>(Rh + o);
                    __nv_bfloat162 rl = *reinterpret_cast<const __nv_bfloat162*>(Rl + o);
                    v0 += __bfloat162float(rh.x) + __bfloat162float(rl.x);
                    v1 += __bfloat162float(rh.y) + __bfloat162float(rl.y);
                }
                if (flags & 4) {
                    *reinterpret_cast<float2*>(C + o) = make_float2(v0, v1);
                }
                if (flags & 8) {
                    bf16 h0, l0, h1, l1;
                    split2(v0, h0, l0); split2(v1, h1, l1);
                    *reinterpret_cast<__nv_bfloat162*>(Ch + o) = __nv_bfloat162(h0, h1);
                    *reinterpret_cast<__nv_bfloat162*>(Cl + o) = __nv_bfloat162(l0, l1);
                }
            }
        }
    }
}

// ---------------------------------------------------------------------------
// Grouped weight prep
// ---------------------------------------------------------------------------
__global__ void transpose_group3(const float* __restrict__ W0, const float* __restrict__ W1,
                                 const float* __restrict__ W2,
                                 bf16* __restrict__ T0h, bf16* __restrict__ T0l,
                                 bf16* __restrict__ T1h, bf16* __restrict__ T1l,
                                 bf16* __restrict__ T2h, bf16* __restrict__ T2l)
{
    int w = blockIdx.y;
    const float* W = (w == 0) ? W0 : (w == 1) ? W1 : W2;
    bf16* Th = (w == 0) ? T0h : (w == 1) ? T1h : T2h;
    bf16* Tl = (w == 0) ? T0l : (w == 1) ? T1l : T2l;
    int n = blockIdx.x;
    for (int k = threadIdx.x; k < 256; k += 128) {
        float v = W[(size_t)k * 512 + n];
        bf16 h, l; split2(v, h, l);
        Th[(size_t)n * 256 + k] = h;
        Tl[(size_t)n * 256 + k] = l;
    }
}

// Group5: W_in (Kp=96 now), We2, Ws, Wt2, Wp2; N=256 all.
__global__ void transpose_group5(const float* __restrict__ Win, const float* __restrict__ We2,
                                 const float* __restrict__ Ws,  const float* __restrict__ Wt2,
                                 const float* __restrict__ Wp2,
                                 bf16* __restrict__ T0h, bf16* __restrict__ T0l,
                                 bf16* __restrict__ T1h, bf16* __restrict__ T1l,
                                 bf16* __restrict__ T2h, bf16* __restrict__ T2l,
                                 bf16* __restrict__ T3h, bf16* __restrict__ T3l,
                                 bf16* __restrict__ T4h, bf16* __restrict__ T4l)
{
    int w = blockIdx.y;
    const float* Wt[5] = {Win, We2, Ws, Wt2, Wp2};
    bf16* Tht[5] = {T0h, T1h, T2h, T3h, T4h};
    bf16* Tlt[5] = {T0l, T1l, T2l, T3l, T4l};
    const int Ks [5] = {96, 512, 256, 512, 512};
    const int Kps[5] = {96, 512, 256, 512, 512};
    const float* W = Wt[w];
    bf16* Th = Tht[w];
    bf16* Tl = Tlt[w];
    int K = Ks[w], Kp = Kps[w];
    int n = blockIdx.x;
    for (int k = threadIdx.x; k < Kp; k += 128) {
        float v = (k < K) ? W[(size_t)k * 256 + n] : 0.f;
        bf16 h, l; split2(v, h, l);
        Th[(size_t)n * Kp + k] = h;
        Tl[(size_t)n * Kp + k] = l;
    }
}

// input split: 96-wide rows (no pad)
__global__ __launch_bounds__(128)
void split_x_all(const float* __restrict__ cand, const float* __restrict__ q,
                 bf16* __restrict__ Xh, bf16* __restrict__ Xl)
{
    size_t r = blockIdx.x;
    int t = threadIdx.x;
    if (t >= NNUM) return;
    const float* src = (r < NCAND) ? (cand + r * NNUM) : (q + (r - NCAND) * NNUM);
    float v = src[t];
    bf16 h, l; split2(v, h, l);
    Xh[r * 96 + t] = h;
    Xl[r * 96 + t] = l;
}

// ---------------------------------------------------------------------------
// Warp-per-row LayerNorm from SPLIT input -> split output
// ---------------------------------------------------------------------------
__global__ __launch_bounds__(256)
void ln_split_warp2(const bf16* __restrict__ Hh, const bf16* __restrict__ Hl,
                    const float* __restrict__ g, const float* __restrict__ b,
                    bf16* __restrict__ Yh, bf16* __restrict__ Yl, int nrows)
{
    int row = blockIdx.x * 8 + (threadIdx.x >> 5);
    int lane = threadIdx.x & 31;
    if (row >= nrows) return;
    uint4 uh = *reinterpret_cast<const uint4*>(Hh + (size_t)row * DM + lane * 8);
    uint4 ul = *reinterpret_cast<const uint4*>(Hl + (size_t)row * DM + lane * 8);
    const bf16* ph = reinterpret_cast<const bf16*>(&uh);
    const bf16* pl = reinterpret_cast<const bf16*>(&ul);
    float fv[8];
    float s = 0.f;
    #pragma unroll
    for (int i = 0; i < 8; i++) {
        fv[i] = __bfloat162float(ph[i]) + __bfloat162float(pl[i]);
        s += fv[i];
    }
    float mu = warp_sum(s) * (1.f / DM);
    float vs = 0.f;
    #pragma unroll
    for (int i = 0; i < 8; i++) { fv[i] -= mu; vs += fv[i] * fv[i]; }
    float rstd = rsqrtf(warp_sum(vs) * (1.f / DM) + 1e-5f);
    float4 g0 = *reinterpret_cast<const float4*>(g + lane * 8);
    float4 g1 = *reinterpret_cast<const float4*>(g + lane * 8 + 4);
    float4 b0 = *reinterpret_cast<const float4*>(b + lane * 8);
    float4 b1 = *reinterpret_cast<const float4*>(b + lane * 8 + 4);
    float gr[8] = {g0.x, g0.y, g0.z, g0.w, g1.x, g1.y, g1.z, g1.w};
    float br[8] = {b0.x, b0.y, b0.z, b0.w, b1.x, b1.y, b1.z, b1.w};
    bf16 hv[8], lv[8];
    #pragma unroll
    for (int i = 0; i < 8; i++) {
        float y = fv[i] * rstd * gr[i] + br[i];
        split2(y, hv[i], lv[i]);
    }
    *reinterpret_cast<uint4*>(Yh + (size_t)row * DM + lane * 8) = *reinterpret_cast<uint4*>(hv);
    *reinterpret_cast<uint4*>(Yl + (size_t)row * DM + lane * 8) = *reinterpret_cast<uint4*>(lv);
}

__global__ __launch_bounds__(256)
void halfnorm_neg_warp(const bf16* __restrict__ Kh, const bf16* __restrict__ Kl,
                       float* __restrict__ hn, int nrows)
{
    int row = blockIdx.x * 8 + (threadIdx.x >> 5);
    int lane = threadIdx.x & 31;
    if (row >= nrows) return;
    uint4 uh = *reinterpret_cast<const uint4*>(Kh + (size_t)row * DM + lane * 8);
    uint4 ul = *reinterpret_cast<const uint4*>(Kl + (size_t)row * DM + lane * 8);
    const bf16* ph = reinterpret_cast<const bf16*>(&uh);
    const bf16* pl = reinterpret_cast<const bf16*>(&ul);
    float s = 0.f;
    #pragma unroll
    for (int i = 0; i < 8; i++) {
        float v = __bfloat162float(ph[i]) + __bfloat162float(pl[i]);
        s += v * v;
    }
    float tot = warp_sum(s);
    if (lane == 0) hn[row] = -0.5f * tot;
}

// ---------------------------------------------------------------------------
// Top-96 + softmax: two-scan compaction (proven) with fallback.
// ---------------------------------------------------------------------------
#define TKCAP 4096
#define TK_SMEM 81920

__device__ __forceinline__ unsigned f2o(float f) {
    unsigned u = __float_as_uint(f);
    return (u & 0x80000000u) ? ~u : (u | 0x80000000u);
}

__global__ __launch_bounds__(256)
void topk_softmax_kernel(const float* __restrict__ score, int N,
                         int* __restrict__ out_idx, float* __restrict__ out_probs)
{
    extern __shared__ unsigned char tks[];
    unsigned* hist = (unsigned*)tks;
    float* v0 = (float*)(tks + 16384);
    int*   i0 = (int*)  (tks + 32768);
    float* v1 = (float*)(tks + 49152);
    int*   i1 = (int*)  (tks + 65536);

    int row = blockIdx.x;
    const float* s = score + (size_t)row * N;
    int tid = threadIdx.x;
    int lane = tid & 31;

    __shared__ float tvals[MCTX];
    __shared__ int   tinds[MCTX];
    __shared__ int cnt_top, cnt_c, cnt_c2, cnt_eq;
    __shared__ unsigned sh_sel;
    __shared__ int sh_krem;
    __shared__ float s_max, s_sum;
    __shared__ float evals[MCTX];

    for (int b = tid; b < 4096; b += 256) hist[b] = 0;
    if (tid == 0) { cnt_top = 0; cnt_c = 0; cnt_c2 = 0; cnt_eq = 0; }
    __syncthreads();
    for (int j = tid; j < N; j += 256) {
        unsigned bin = f2o(s[j]) >> 20;
        unsigned peers = __match_any_sync(0xffffffffu, bin);
        int leader = __ffs(peers) - 1;
        if (lane == leader) atomicAdd(&hist[bin], __popc(peers));
    }
    __syncthreads();
    if (tid == 0) {
        int cum = 0;
        unsigned bsel = 0;
        for (int b = 4095; b >= 0; b--) {
            int c = (int)hist[b];
            if (cum + c >= MCTX) { bsel = (unsigned)b; break; }
            cum += c;
        }
        sh_sel = bsel;
        sh_krem = MCTX - cum;
    }
    __syncthreads();
    unsigned sel = sh_sel;

    for (int j = tid; j < N; j += 256) {
        float f = s[j];
        unsigned b = f2o(f) >> 20;
        if (b > sel) {
            int p = atomicAdd(&cnt_top, 1);
            tvals[p] = f; tinds[p] = j;
        } else if (b == sel) {
            int p = atomicAdd(&cnt_c, 1);
            if (p < TKCAP) { v0[p] = f; i0[p] = j; }
        }
    }
    __syncthreads();

    if (cnt_c <= TKCAP) {
        int nc = cnt_c;
        int krem = sh_krem;
        for (int b = tid; b < 4096; b += 256) hist[b] = 0;
        __syncthreads();
        for (int t = tid; t < nc; t += 256)
            atomicAdd(&hist[(f2o(v0[t]) >> 8) & 0xFFFu], 1);
        __syncthreads();
        if (tid == 0) {
            int cum = 0;
            unsigned bsel = 0;
            for (int b = 4095; b >= 0; b--) {
                int c = (int)hist[b];
                if (cum + c >= krem) { bsel = (unsigned)b; break; }
                cum += c;
            }
            sh_sel = bsel;
            sh_krem = krem - cum;
        }
        __syncthreads();
        unsigned sel2 = sh_sel;
        for (int t = tid; t < nc; t += 256) {
            float f = v0[t];
            unsigned m = (f2o(f) >> 8) & 0xFFFu;
            if (m > sel2) {
                int p = atomicAdd(&cnt_top, 1);
                tvals[p] = f; tinds[p] = i0[t];
            } else if (m == sel2) {
                int p = atomicAdd(&cnt_c2, 1);
                v1[p] = f; i1[p] = i0[t];
            }
        }
        __syncthreads();

        int nc2 = cnt_c2;
        int krem2 = sh_krem;
        for (int b = tid; b < 256; b += 256) hist[b] = 0;
        __syncthreads();
        for (int t = tid; t < nc2; t += 256)
            atomicAdd(&hist[f2o(v1[t]) & 0xFFu], 1);
        __syncthreads();
        if (tid == 0) {
            int cum = 0;
            unsigned bsel = 0;
            for (int b = 255; b >= 0; b--) {
                int c = (int)hist[b];
                if (cum + c >= krem2) { bsel = (unsigned)b; break; }
                cum += c;
            }
            sh_sel = bsel;
            sh_krem = krem2 - cum;
        }
        __syncthreads();
        unsigned sel3 = sh_sel;
        int need = sh_krem;
        for (int t = tid; t < nc2; t += 256) {
            float f = v1[t];
            unsigned lo = f2o(f) & 0xFFu;
            if (lo > sel3) {
                int p = atomicAdd(&cnt_top, 1);
                tvals[p] = f; tinds[p] = i1[t];
            } else if (lo == sel3) {
                int p = atomicAdd(&cnt_eq, 1);
                if (p < need) {
                    int q = atomicAdd(&cnt_top, 1);
                    tvals[q] = f; tinds[q] = i1[t];
                }
            }
        }
        __syncthreads();
    } else {
        __syncthreads();
        if (tid == 0) { cnt_top = 0; cnt_eq = 0; sh_sel = 0u; sh_krem = MCTX; }
        __syncthreads();
        int nIter = (N + 255) / 256;
        for (int shift = 24; shift >= 0; shift -= 8) {
            for (int b = tid; b < 256; b += 256) hist[b] = 0;
            __syncthreads();
            unsigned prefix = sh_sel;
            unsigned mask_hi = (shift == 24) ? 0u : (0xFFFFFFFFu << (shift + 8));
            for (int it = 0; it < nIter; it++) {
                int j = it * 256 + tid;
                bool act = false;
                unsigned bin = 0;
                if (j < N) {
                    unsigned u = f2o(s[j]);
                    act = ((u & mask_hi) == prefix);
                    bin = (u >> shift) & 255u;
                }
                int key = act ? (int)bin : (256 + lane);
                unsigned peers = __match_any_sync(0xffffffffu, key);
                int leader = __ffs(peers) - 1;
                if (act && lane == leader) atomicAdd(&hist[bin], __popc(peers));
            }
            __syncthreads();
            if (tid == 0) {
                int kr = sh_krem;
                int cum = 0, bsel = 0;
                for (int bb = 255; bb >= 0; bb--) {
                    int c = (int)hist[bb];
                    if (cum + c >= kr) { bsel = bb; break; }
                    cum += c;
                }
                sh_sel = prefix | ((unsigned)bsel << shift);
                sh_krem = kr - cum;
            }
            __syncthreads();
        }
        unsigned T = sh_sel;
        int need = sh_krem;
        for (int j = tid; j < N; j += 256) {
            float f = s[j];
            unsigned u = f2o(f);
            if (u > T) {
                int p = atomicAdd(&cnt_top, 1);
                tvals[p] = f; tinds[p] = j;
            } else if (u == T) {
                int p = atomicAdd(&cnt_eq, 1);
                if (p < need) {
                    int q = atomicAdd(&cnt_top, 1);
                    tvals[q] = f; tinds[q] = j;
                }
            }
        }
        __syncthreads();
    }

    if (tid == 0) {
        float mx = -1e30f;
        for (int m = 0; m < MCTX; m++) mx = fmaxf(mx, 2.f * tvals[m]);
        s_max = mx;
    }
    __syncthreads();
    if (tid < MCTX) evals[tid] = expf(2.f * tvals[tid] - s_max);
    __syncthreads();
    if (tid == 0) {
        float sm = 0.f;
        for (int m = 0; m < MCTX; m++) sm += evals[m];
        s_sum = sm;
    }
    __syncthreads();
    if (tid < MCTX) {
        out_probs[row * MCTX + tid] = evals[tid] / s_sum;
        out_idx[row * MCTX + tid]   = tinds[tid];
    }
}

// ---------------------------------------------------------------------------
// Warp-per-row D build from split keys (8 rows per CTA, uint4 IO)
// ---------------------------------------------------------------------------
__global__ __launch_bounds__(256)
void build_d_split_warp(const bf16* __restrict__ Kh, const bf16* __restrict__ Kl,
                        const int* __restrict__ idx,
                        bf16* __restrict__ Dh, bf16* __restrict__ Dl, int nrows)
{
    int r = blockIdx.x * 8 + (threadIdx.x >> 5);
    int lane = threadIdx.x & 31;
    if (r >= nrows) return;
    int b = r / MCTX;
    int j = idx[r];
    size_t oq = (size_t)(NCAND + b) * DM + lane * 8;
    size_t oc = (size_t)j * DM + lane * 8;
    uint4 qh = *reinterpret_cast<const uint4*>(Kh + oq);
    uint4 ql = *reinterpret_cast<const uint4*>(Kl + oq);
    uint4 ch = *reinterpret_cast<const uint4*>(Kh + oc);
    uint4 cl = *reinterpret_cast<const uint4*>(Kl + oc);
    const bf16* pqh = reinterpret_cast<const bf16*>(&qh);
    const bf16* pql = reinterpret_cast<const bf16*>(&ql);
    const bf16* pch = reinterpret_cast<const bf16*>(&ch);
    const bf16* pcl = reinterpret_cast<const bf16*>(&cl);
    bf16 hv[8], lv[8];
    #pragma unroll
    for (int i = 0; i < 8; i++) {
        float kq = __bfloat162float(pqh[i]) + __bfloat162float(pql[i]);
        float kc = __bfloat162float(pch[i]) + __bfloat162float(pcl[i]);
        split2(kq - kc, hv[i], lv[i]);
    }
    *reinterpret_cast<uint4*>(Dh + (size_t)r * DM + lane * 8) = *reinterpret_cast<uint4*>(hv);
    *reinterpret_cast<uint4*>(Dl + (size_t)r * DM + lane * 8) = *reinterpret_cast<uint4*>(lv);
}

// ---------------------------------------------------------------------------
// Combine (h from split pair)
// ---------------------------------------------------------------------------
__global__ __launch_bounds__(256)
void combine_kernel(const bf16* __restrict__ Hh, const bf16* __restrict__ Hl,
                    const float* __restrict__ U,
                    const float* __restrict__ probs, const int* __restrict__ idx,
                    const float* __restrict__ cand_y, const float* __restrict__ Wy,
                    const float* __restrict__ by, const float* __restrict__ bt2,
                    float* __restrict__ xout, bf16* __restrict__ Xh, bf16* __restrict__ Xl)
{
    int b = blockIdx.x;
    int tid = threadIdx.x;
    __shared__ float p_s[MCTX];
    __shared__ float py_s[MCTX];
    __shared__ float ybar_s;
    if (tid < MCTX) {
        float p = probs[b * MCTX + tid];
        p_s[tid] = p;
        py_s[tid] = p * cand_y[idx[b * MCTX + tid]];
    }
    __syncthreads();
    if (tid == 0) {
        float yb = 0.f;
        for (int m = 0; m < MCTX; m++) yb += py_s[m];
        ybar_s = yb;
    }
    __syncthreads();
    const float* Ub = U + (size_t)b * MCTX * DM;
    float acc = 0.f;
    #pragma unroll 4
    for (int m = 0; m < MCTX; m++) acc += p_s[m] * Ub[(size_t)m * DM + tid];
    size_t ho = (size_t)(NCAND + b) * DM + tid;
    float hres = __bfloat162float(Hh[ho]) + __bfloat162float(Hl[ho]);
    float v = hres + acc + ybar_s * Wy[tid] + by[tid] + bt2[tid];
    xout[b * DM + tid] = v;
    bf16 hh, ll; split2(v, hh, ll);
    Xh[b * DM + tid] = hh;
    Xl[b * DM + tid] = ll;
}

// ---------------------------------------------------------------------------
// Head
// ---------------------------------------------------------------------------
__global__ __launch_bounds__(256)
void head_kernel(const float* __restrict__ X, const float* __restrict__ g,
                 const float* __restrict__ b, const float* __restrict__ Wh,
                 const float* __restrict__ bh, float* __restrict__ out)
{
    int r = blockIdx.x;
    int tid = threadIdx.x;
    float x = X[(size_t)r * DM + tid];
    float mu = block_sum_256(x) * (1.f / DM);
    float d = x - mu;
    float var = block_sum_256(d * d) * (1.f / DM);
    float y = d * rsqrtf(var + 1e-5f) * g[tid] + b[tid];
    float t = fmaxf(y, 0.f) * Wh[tid];
    float tot = block_sum_256(t);
    if (tid == 0) out[r] = tot + bh[0];
}

// ---------------------------------------------------------------------------
// Launcher
// ---------------------------------------------------------------------------
#define GETSYM(var, sym) cudaGetSymbolAddress((void**)&(var), sym)

extern "C" void kernel_launch(void* const* d_in, const int* in_sizes, int n_in,
                              void* d_out, int out_size)
{
    const float* x_num  = (const float*)d_in[0];
    const float* cand_x = (const float*)d_in[1];
    const float* cand_y = (const float*)d_in[2];
    int off = (n_in >= 27) ? 1 : 0;
    int i = 3 + off;
    const float* W_in = (const float*)d_in[i++]; const float* b_in = (const float*)d_in[i++];
    const float* We1  = (const float*)d_in[i++]; const float* be1  = (const float*)d_in[i++];
    const float* We2  = (const float*)d_in[i++]; const float* be2  = (const float*)d_in[i++];
    const float* g_m  = (const float*)d_in[i++]; const float* b_m  = (const float*)d_in[i++];
    const float* Ws   = (const float*)d_in[i++]; const float* bs   = (const float*)d_in[i++];
    const float* Wy   = (const float*)d_in[i++]; const float* by   = (const float*)d_in[i++];
    const float* Wt1  = (const float*)d_in[i++];
    const float* Wt2  = (const float*)d_in[i++]; const float* bt2  = (const float*)d_in[i++];
    const float* Wp1  = (const float*)d_in[i++]; const float* bp1  = (const float*)d_in[i++];
    const float* Wp2  = (const float*)d_in[i++]; const float* bp2  = (const float*)d_in[i++];
    const float* g_h  = (const float*)d_in[i++]; const float* b_h  = (const float*)d_in[i++];
    const float* Wh   = (const float*)d_in[i++]; const float* bh   = (const float*)d_in[i++];
    float* out = (float*)d_out;

    cudaFuncSetAttribute(gemm_mma, cudaFuncAttributeMaxDynamicSharedMemorySize, GEMM_SMEM);
    cudaFuncSetAttribute(topk_softmax_kernel, cudaFuncAttributeMaxDynamicSharedMemorySize, TK_SMEM);

    float *U, *score, *hnneg, *px, *probs;
    int* idxp;
    GETSYM(U, g_U); GETSYM(score, g_score);
    GETSYM(hnneg, g_hnneg); GETSYM(px, g_px);
    GETSYM(idxp, g_idx); GETSYM(probs, g_probs);

    bf16 *xh,*xl,*h0h,*h0l,*th,*tl,*lnh,*lnl,*ckh,*ckl;
    bf16 *dh,*dl,*t2h,*t2l,*pxh,*pxl,*pth,*ptl;
    GETSYM(xh, g_xh); GETSYM(xl, g_xl);
    GETSYM(h0h, g_h0h); GETSYM(h0l, g_h0l); GETSYM(th, g_th);  GETSYM(tl, g_tl);
    GETSYM(lnh, g_lnh); GETSYM(lnl, g_lnl); GETSYM(ckh, g_ckh); GETSYM(ckl, g_ckl);
    GETSYM(dh, g_dh); GETSYM(dl, g_dl); GETSYM(t2h, g_t2h); GETSYM(t2l, g_t2l);
    GETSYM(pxh, g_pxh); GETSYM(pxl, g_pxl); GETSYM(pth, g_pth); GETSYM(ptl, g_ptl);

    bf16 *winh,*winl,*we1h,*we1l,*we2h,*we2l,*wsh,*wsl,*wt1h,*wt1l,*wt2h,*wt2l,*wp1h,*wp1l,*wp2h,*wp2l;
    GETSYM(winh, g_winh); GETSYM(winl, g_winl);
    GETSYM(we1h, g_we1h); GETSYM(we1l, g_we1l);
    GETSYM(we2h, g_we2h); GETSYM(we2l, g_we2l);
    GETSYM(wsh, g_wsh);   GETSYM(wsl, g_wsl);
    GETSYM(wt1h, g_wt1h); GETSYM(wt1l, g_wt1l);
    GETSYM(wt2h, g_wt2h); GETSYM(wt2l, g_wt2l);
    GETSYM(wp1h, g_wp1h); GETSYM(wp1l, g_wp1l);
    GETSYM(wp2h, g_wp2h); GETSYM(wp2l, g_wp2l);

    // [0..2] prep
    transpose_group3<<<dim3(512, 3), 128>>>(We1, Wt1, Wp1,
                                            we1h, we1l, wt1h, wt1l, wp1h, wp1l);
    transpose_group5<<<dim3(256, 5), 128>>>(W_in, We2, Ws, Wt2, Wp2,
                                            winh, winl, we2h, we2l, wsh, wsl,
                                            wt2h, wt2l, wp2h, wp2l);
    split_x_all<<<NT, 128>>>(cand_x, x_num, xh, xl);

    const int GT = (NT + 127) / 128;     // 790

    // [3..5] combined encode (full 3-segment precision)
    gemm_mma<<<dim3(2, GT), 256, GEMM_SMEM>>>(xh, xl, winh, winl, b_in,
                                              nullptr, nullptr, nullptr,
                                              nullptr, h0h, h0l, NT, 256, 96, 8);
    gemm_mma<<<dim3(4, GT), 256, GEMM_SMEM>>>(h0h, h0l, we1h, we1l, be1,
                                              nullptr, nullptr, nullptr,
                                              nullptr, th, tl, NT, 512, 256, 1 | 8);
    // encode3: residual from split h0, write split h0 in place (no f32 stream)
    gemm_mma<<<dim3(2, GT), 256, GEMM_SMEM>>>(th, tl, we2h, we2l, be2,
                                              nullptr, h0h, h0l,
                                              nullptr, h0h, h0l, NT, 256, 512, 16 | 8);
    ln_split_warp2<<<(NT + 7) / 8, 256>>>(h0h, h0l, g_m, b_m, lnh, lnl, NT);
    gemm_mma<<<dim3(2, GT), 256, GEMM_SMEM>>>(lnh, lnl, wsh, wsl, bs,
                                              nullptr, nullptr, nullptr,
                                              nullptr, ckh, ckl, NT, 256, 256, 8);
    halfnorm_neg_warp<<<(NCAND + 7) / 8, 256>>>(ckh, ckl, hnneg, NCAND);

    // similarity scores — full precision, swapped raster for L2 reuse
    gemm_mma<<<dim3(8, 782), 256, GEMM_SMEM>>>(
        ckh + (size_t)NCAND * DM, ckl + (size_t)NCAND * DM, ckh, ckl, hnneg,
        nullptr, nullptr, nullptr,
        score, nullptr, nullptr, BQ, NCAND, 256, 4 | 32);

    topk_softmax_kernel<<<BQ, 256, TK_SMEM>>>(score, NCAND, idxp, probs);
    build_d_split_warp<<<(RN + 7) / 8, 256>>>(ckh, ckl, idxp, dh, dl, RN);

    // value MLP — 2-segment mode (post-selection)
    gemm_mma<<<dim3(4, 768), 256, GEMM_SMEM>>>(dh, dl, wt1h, wt1l, nullptr,
                                               nullptr, nullptr, nullptr,
                                               nullptr, t2h, t2l, RN, 512, 256, 1 | 8 | 64);
    gemm_mma<<<dim3(2, 768), 256, GEMM_SMEM>>>(t2h, t2l, wt2h, wt2l, nullptr,
                                               nullptr, nullptr, nullptr,
                                               U, nullptr, nullptr, RN, 256, 512, 4 | 64);

    combine_kernel<<<BQ, 256>>>(h0h, h0l, U, probs, idxp, cand_y, Wy, by, bt2,
                                px, pxh, pxl);

    // predictor + head (full precision)
    gemm_mma<<<dim3(4, 8), 256, GEMM_SMEM>>>(pxh, pxl, wp1h, wp1l, bp1,
                                             nullptr, nullptr, nullptr,
                                             nullptr, pth, ptl, BQ, 512, 256, 1 | 8);
    gemm_mma<<<dim3(2, 8), 256, GEMM_SMEM>>>(pth, ptl, wp2h, wp2l, bp2,
                                             px, nullptr, nullptr,
                                             px, nullptr, nullptr, BQ, 256, 512, 2 | 4);
    head_kernel<<<BQ, 256>>>(px, g_h, b_h, Wh, bh, out);

    (void)in_sizes; (void)out_size;
}

// round 14
// speedup vs baseline: 1.3961x; 1.3961x over previous
#include <cuda_runtime.h>
#include <cuda_bf16.h>
#include <math.h>
#include <stdint.h>

// ---------------------------------------------------------------------------
// Problem constants
// ---------------------------------------------------------------------------
#define NCAND 100000
#define BQ    1024
#define NT    (NCAND + BQ)
#define DM    256
#define DH    512
#define NNUM  96
#define MCTX  96
#define RN    (BQ * MCTX)

typedef __nv_bfloat16 bf16;

// ---------------------------------------------------------------------------
// Device scratch
// ---------------------------------------------------------------------------
__device__ float g_U    [(size_t)RN * DM];
__device__ float g_score[(size_t)BQ * NCAND];
__device__ float g_hnneg[NCAND];
__device__ float g_px [BQ * DM];
__device__ int   g_idx [BQ * MCTX];
__device__ float g_probs[BQ * MCTX];

__device__ bf16 g_xh [(size_t)NT * 96],  g_xl [(size_t)NT * 96];
__device__ bf16 g_h0h[(size_t)NT * DM],  g_h0l[(size_t)NT * DM];
__device__ bf16 g_th [(size_t)NT * DH],  g_tl [(size_t)NT * DH];
__device__ bf16 g_lnh[(size_t)NT * DM],  g_lnl[(size_t)NT * DM];
__device__ bf16 g_ckh[(size_t)NT * DM],  g_ckl[(size_t)NT * DM];
__device__ bf16 g_dh [(size_t)RN * DM],  g_dl [(size_t)RN * DM];
__device__ bf16 g_t2h[(size_t)RN * DH],  g_t2l[(size_t)RN * DH];
__device__ bf16 g_pxh[BQ * DM], g_pxl[BQ * DM];
__device__ bf16 g_pth[BQ * DH], g_ptl[BQ * DH];

__device__ bf16 g_winh[256 * 96],  g_winl[256 * 96];
__device__ bf16 g_we1h[512 * 256], g_we1l[512 * 256];
__device__ bf16 g_we2h[256 * 512], g_we2l[256 * 512];
__device__ bf16 g_wsh [256 * 256], g_wsl [256 * 256];
__device__ bf16 g_wt1h[512 * 256], g_wt1l[512 * 256];
__device__ bf16 g_wt2h[256 * 512], g_wt2l[256 * 512];
__device__ bf16 g_wp1h[512 * 256], g_wp1l[512 * 256];
__device__ bf16 g_wp2h[256 * 512], g_wp2l[256 * 512];

// ---------------------------------------------------------------------------
// Helpers
// ---------------------------------------------------------------------------
__device__ __forceinline__ uint32_t smem_u32(const void* p) {
    uint32_t a;
    asm("{ .reg .u64 t; cvta.to.shared.u64 t, %1; cvt.u32.u64 %0, t; }" : "=r"(a) : "l"(p));
    return a;
}

__device__ __forceinline__ void cp16(uint32_t dst, const void* src, bool valid) {
    int sz = valid ? 16 : 0;
    asm volatile("cp.async.cg.shared.global [%0], [%1], 16, %2;"
                 :: "r"(dst), "l"(src), "r"(sz));
}
#define CP_COMMIT() asm volatile("cp.async.commit_group;")
#define CP_WAIT(n)  asm volatile("cp.async.wait_group %0;" :: "n"(n))

__device__ __forceinline__ void ldsm4(uint32_t addr, uint32_t& r0, uint32_t& r1,
                                      uint32_t& r2, uint32_t& r3) {
    asm volatile("ldmatrix.sync.aligned.m8n8.x4.shared.b16 {%0,%1,%2,%3}, [%4];"
                 : "=r"(r0), "=r"(r1), "=r"(r2), "=r"(r3) : "r"(addr));
}

__device__ __forceinline__ void mma16816(float* c, const uint32_t* a, const uint32_t* b) {
    asm volatile(
        "mma.sync.aligned.m16n8k16.row.col.f32.bf16.bf16.f32 "
        "{%0,%1,%2,%3}, {%4,%5,%6,%7}, {%8,%9}, {%0,%1,%2,%3};"
        : "+f"(c[0]), "+f"(c[1]), "+f"(c[2]), "+f"(c[3])
        : "r"(a[0]), "r"(a[1]), "r"(a[2]), "r"(a[3]), "r"(b[0]), "r"(b[1]));
}

__device__ __forceinline__ float block_sum_256(float v) {
    __shared__ float sh[8];
    int lane = threadIdx.x & 31, w = threadIdx.x >> 5;
    #pragma unroll
    for (int o = 16; o > 0; o >>= 1) v += __shfl_xor_sync(0xffffffffu, v, o);
    __syncthreads();
    if (lane == 0) sh[w] = v;
    __syncthreads();
    float t = sh[0];
    #pragma unroll
    for (int i = 1; i < 8; i++) t += sh[i];
    return t;
}

__device__ __forceinline__ float warp_sum(float v) {
    #pragma unroll
    for (int o = 16; o > 0; o >>= 1) v += __shfl_xor_sync(0xffffffffu, v, o);
    return v;
}

__device__ __forceinline__ void split2(float v, bf16& h, bf16& l) {
    h = __float2bfloat16(v);
    l = __float2bfloat16(v - __bfloat162float(h));
}

// ---------------------------------------------------------------------------
// gemm_mma: FROZEN round-10/12 core. (issue -> wait -> BARRIER -> compute;
// the barrier after CP_WAIT is what makes cross-thread cp.async data visible.)
// flags: 1 relu, 2 +res(f32), 4 write f32 C, 8 write split (Ch,Cl),
//        16 +res split (Rh+Rl), 32 swap block-index mapping, 64 two-segment
// ---------------------------------------------------------------------------
#define LDA 40
#define STG_ELEM (128 * LDA)
#define STAGE_BYTES (2 * STG_ELEM * 2)
#define NSTAGE 5
#define GEMM_SMEM (NSTAGE * STAGE_BYTES)

__global__ __launch_bounds__(256, 2)
void gemm_mma(const bf16* __restrict__ Ah, const bf16* __restrict__ Al,
              const bf16* __restrict__ Bh, const bf16* __restrict__ Bl,
              const float* __restrict__ bias, const float* __restrict__ res,
              const bf16* __restrict__ Rh, const bf16* __restrict__ Rl,
              float* __restrict__ C, bf16* __restrict__ Ch, bf16* __restrict__ Cl,
              int M, int N, int Kp, int flags)
{
    extern __shared__ __align__(16) bf16 sdyn[];
    __shared__ float sbias[128];

    const int tid  = threadIdx.x;
    const int lane = tid & 31;
    const int wid  = tid >> 5;
    const int wm   = wid & 3;
    const int wn   = wid >> 2;
    const int bm   = ((flags & 32) ? blockIdx.x : blockIdx.y) * 128;
    const int bn   = ((flags & 32) ? blockIdx.y : blockIdx.x) * 128;

    if (tid < 128) {
        int col = bn + tid;
        sbias[tid] = (bias != nullptr && col < N) ? bias[col] : 0.f;
    }

    const uint32_t sBase = smem_u32(sdyn);

    const bf16* segA[3] = {Ah, Ah, Al};
    const bf16* segB[3] = {Bh, Bl, Bh};
    if (flags & 64) { segA[1] = Al; segB[1] = Bh; }
    const int nseg = (flags & 64) ? 2 : 3;
    const int nk = Kp >> 5;
    const int NC = nseg * nk;

    float acc[2][8][4];
    #pragma unroll
    for (int t = 0; t < 2; t++)
        #pragma unroll
        for (int j = 0; j < 8; j++)
            #pragma unroll
            for (int e = 0; e < 4; e++) acc[t][j][e] = 0.f;

    auto issue = [&](int c, int st) {
        int seg = c / nk;
        int k0  = (c - seg * nk) << 5;
        const bf16* Ap = segA[seg];
        const bf16* Bp = segB[seg];
        uint32_t stA = sBase + (uint32_t)(st * STAGE_BYTES);
        uint32_t stB = stA + STG_ELEM * 2;
        #pragma unroll
        for (int h = 0; h < 2; h++) {
            int q   = tid + h * 256;
            int row = q >> 2;
            int sg  = q & 3;
            uint32_t off = (uint32_t)(row * 80 + sg * 16);
            int ar = bm + row; bool av = ar < M; if (!av) ar = 0;
            cp16(stA + off, Ap + (size_t)ar * Kp + k0 + sg * 8, av);
            int br = bn + row; bool bv = br < N; if (!bv) br = 0;
            cp16(stB + off, Bp + (size_t)br * Kp + k0 + sg * 8, bv);
        }
        CP_COMMIT();
    };

    issue(0, 0);
    issue(1, 1);
    issue(2, 2);
    int st_w = 3, st_r = 0;
    for (int c = 0; c < NC; ++c) {
        if (c + 3 < NC) {
            issue(c + 3, st_w);
            if (++st_w == NSTAGE) st_w = 0;
        } else {
            CP_COMMIT();
        }
        CP_WAIT(3);
        __syncthreads();

        uint32_t stA = sBase + (uint32_t)(st_r * STAGE_BYTES);
        uint32_t stB = stA + STG_ELEM * 2;
        if (++st_r == NSTAGE) st_r = 0;
        uint32_t aBase = stA + (uint32_t)((wm * 32) * 80);
        uint32_t bBase = stB + (uint32_t)((wn * 64) * 80);

        #pragma unroll
        for (int ks = 0; ks < 32; ks += 16) {
            uint32_t a[2][4];
            #pragma unroll
            for (int t = 0; t < 2; t++) {
                uint32_t addr = aBase + (uint32_t)((t * 16 + (lane & 15)) * 80
                                                   + (ks + (lane >> 4) * 8) * 2);
                ldsm4(addr, a[t][0], a[t][1], a[t][2], a[t][3]);
            }
            uint32_t b[8][2];
            #pragma unroll
            for (int jp = 0; jp < 4; jp++) {
                int grp = lane >> 3;
                int row = jp * 16 + (grp >> 1) * 8 + (lane & 7);
                int kof = (grp & 1) * 8;
                uint32_t addr = bBase + (uint32_t)(row * 80 + (ks + kof) * 2);
                ldsm4(addr, b[2 * jp][0], b[2 * jp][1], b[2 * jp + 1][0], b[2 * jp + 1][1]);
            }
            #pragma unroll
            for (int t = 0; t < 2; t++)
                #pragma unroll
                for (int j = 0; j < 8; j++)
                    mma16816(acc[t][j], a[t], b[j]);
        }
    }

    // ---- epilogue ----
    int colb = (lane & 3) * 2;
    #pragma unroll
    for (int t = 0; t < 2; t++) {
        int row0 = bm + wm * 32 + t * 16 + (lane >> 2);
        #pragma unroll
        for (int j = 0; j < 8; j++) {
            int col = bn + wn * 64 + j * 8 + colb;
            if (col >= N) continue;
            #pragma unroll
            for (int half = 0; half < 2; half++) {
                int rr = row0 + half * 8;
                if (rr >= M) continue;
                float v0 = acc[t][j][half * 2 + 0];
                float v1 = acc[t][j][half * 2 + 1];
                int cl = col - bn;
                v0 += sbias[cl]; v1 += sbias[cl + 1];
                if (flags & 1) { v0 = fmaxf(v0, 0.f); v1 = fmaxf(v1, 0.f); }
                size_t o = (size_t)rr * N + col;
                if (flags & 2) {
                    float2 r2 = *reinterpret_cast<const float2*>(res + o);
                    v0 += r2.x; v1 += r2.y;
                }
                if (flags & 16) {
                    __nv_bfloat162 rh = *reinterpret_cast<const __nv_bfloat162*>(Rh + o);
                    __nv_bfloat162 rl = *reinterpret_cast<const __nv_bfloat162*>(Rl + o);
                    v0 += __bfloat162float(rh.x) + __bfloat162float(rl.x);
                    v1 += __bfloat162float(rh.y) + __bfloat162float(rl.y);
                }
                if (flags & 4) {
                    *reinterpret_cast<float2*>(C + o) = make_float2(v0, v1);
                }
                if (flags & 8) {
                    bf16 h0, l0, h1, l1;
                    split2(v0, h0, l0); split2(v1, h1, l1);
                    *reinterpret_cast<__nv_bfloat162*>(Ch + o) = __nv_bfloat162(h0, h1);
                    *reinterpret_cast<__nv_bfloat162*>(Cl + o) = __nv_bfloat162(l0, l1);
                }
            }
        }
    }
}

// ---------------------------------------------------------------------------
// Grouped weight prep
// ---------------------------------------------------------------------------
__global__ void transpose_group3(const float* __restrict__ W0, const float* __restrict__ W1,
                                 const float* __restrict__ W2,
                                 bf16* __restrict__ T0h, bf16* __restrict__ T0l,
                                 bf16* __restrict__ T1h, bf16* __restrict__ T1l,
                                 bf16* __restrict__ T2h, bf16* __restrict__ T2l)
{
    int w = blockIdx.y;
    const float* W = (w == 0) ? W0 : (w == 1) ? W1 : W2;
    bf16* Th = (w == 0) ? T0h : (w == 1) ? T1h : T2h;
    bf16* Tl = (w == 0) ? T0l : (w == 1) ? T1l : T2l;
    int n = blockIdx.x;
    for (int k = threadIdx.x; k < 256; k += 128) {
        float v = W[(size_t)k * 512 + n];
        bf16 h, l; split2(v, h, l);
        Th[(size_t)n * 256 + k] = h;
        Tl[(size_t)n * 256 + k] = l;
    }
}

__global__ void transpose_group5(const float* __restrict__ Win, const float* __restrict__ We2,
                                 const float* __restrict__ Ws,  const float* __restrict__ Wt2,
                                 const float* __restrict__ Wp2,
                                 bf16* __restrict__ T0h, bf16* __restrict__ T0l,
                                 bf16* __restrict__ T1h, bf16* __restrict__ T1l,
                                 bf16* __restrict__ T2h, bf16* __restrict__ T2l,
                                 bf16* __restrict__ T3h, bf16* __restrict__ T3l,
                                 bf16* __restrict__ T4h, bf16* __restrict__ T4l)
{
    int w = blockIdx.y;
    const float* Wt[5] = {Win, We2, Ws, Wt2, Wp2};
    bf16* Tht[5] = {T0h, T1h, T2h, T3h, T4h};
    bf16* Tlt[5] = {T0l, T1l, T2l, T3l, T4l};
    const int Ks [5] = {96, 512, 256, 512, 512};
    const int Kps[5] = {96, 512, 256, 512, 512};
    const float* W = Wt[w];
    bf16* Th = Tht[w];
    bf16* Tl = Tlt[w];
    int K = Ks[w], Kp = Kps[w];
    int n = blockIdx.x;
    for (int k = threadIdx.x; k < Kp; k += 128) {
        float v = (k < K) ? W[(size_t)k * 256 + n] : 0.f;
        bf16 h, l; split2(v, h, l);
        Th[(size_t)n * Kp + k] = h;
        Tl[(size_t)n * Kp + k] = l;
    }
}

// grid-stride input split over NT*96 elements
__global__ __launch_bounds__(256)
void split_x_all(const float* __restrict__ cand, const float* __restrict__ q,
                 bf16* __restrict__ Xh, bf16* __restrict__ Xl)
{
    size_t total = (size_t)NT * NNUM;
    for (size_t e = (size_t)blockIdx.x * 256 + threadIdx.x; e < total;
         e += (size_t)gridDim.x * 256) {
        size_t r = e / NNUM;
        int t = (int)(e - r * NNUM);
        float v = (r < NCAND) ? cand[r * NNUM + t] : q[(r - NCAND) * NNUM + t];
        bf16 h, l; split2(v, h, l);
        Xh[e] = h;
        Xl[e] = l;
    }
}

// ---------------------------------------------------------------------------
// Warp-per-row LayerNorm from SPLIT input -> split output
// ---------------------------------------------------------------------------
__global__ __launch_bounds__(256)
void ln_split_warp2(const bf16* __restrict__ Hh, const bf16* __restrict__ Hl,
                    const float* __restrict__ g, const float* __restrict__ b,
                    bf16* __restrict__ Yh, bf16* __restrict__ Yl, int nrows)
{
    int row = blockIdx.x * 8 + (threadIdx.x >> 5);
    int lane = threadIdx.x & 31;
    if (row >= nrows) return;
    uint4 uh = *reinterpret_cast<const uint4*>(Hh + (size_t)row * DM + lane * 8);
    uint4 ul = *reinterpret_cast<const uint4*>(Hl + (size_t)row * DM + lane * 8);
    const bf16* ph = reinterpret_cast<const bf16*>(&uh);
    const bf16* pl = reinterpret_cast<const bf16*>(&ul);
    float fv[8];
    float s = 0.f;
    #pragma unroll
    for (int i = 0; i < 8; i++) {
        fv[i] = __bfloat162float(ph[i]) + __bfloat162float(pl[i]);
        s += fv[i];
    }
    float mu = warp_sum(s) * (1.f / DM);
    float vs = 0.f;
    #pragma unroll
    for (int i = 0; i < 8; i++) { fv[i] -= mu; vs += fv[i] * fv[i]; }
    float rstd = rsqrtf(warp_sum(vs) * (1.f / DM) + 1e-5f);
    float4 g0 = *reinterpret_cast<const float4*>(g + lane * 8);
    float4 g1 = *reinterpret_cast<const float4*>(g + lane * 8 + 4);
    float4 b0 = *reinterpret_cast<const float4*>(b + lane * 8);
    float4 b1 = *reinterpret_cast<const float4*>(b + lane * 8 + 4);
    float gr[8] = {g0.x, g0.y, g0.z, g0.w, g1.x, g1.y, g1.z, g1.w};
    float br[8] = {b0.x, b0.y, b0.z, b0.w, b1.x, b1.y, b1.z, b1.w};
    bf16 hv[8], lv[8];
    #pragma unroll
    for (int i = 0; i < 8; i++) {
        float y = fv[i] * rstd * gr[i] + br[i];
        split2(y, hv[i], lv[i]);
    }
    *reinterpret_cast<uint4*>(Yh + (size_t)row * DM + lane * 8) = *reinterpret_cast<uint4*>(hv);
    *reinterpret_cast<uint4*>(Yl + (size_t)row * DM + lane * 8) = *reinterpret_cast<uint4*>(lv);
}

__global__ __launch_bounds__(256)
void halfnorm_neg_warp(const bf16* __restrict__ Kh, const bf16* __restrict__ Kl,
                       float* __restrict__ hn, int nrows)
{
    int row = blockIdx.x * 8 + (threadIdx.x >> 5);
    int lane = threadIdx.x & 31;
    if (row >= nrows) return;
    uint4 uh = *reinterpret_cast<const uint4*>(Kh + (size_t)row * DM + lane * 8);
    uint4 ul = *reinterpret_cast<const uint4*>(Kl + (size_t)row * DM + lane * 8);
    const bf16* ph = reinterpret_cast<const bf16*>(&uh);
    const bf16* pl = reinterpret_cast<const bf16*>(&ul);
    float s = 0.f;
    #pragma unroll
    for (int i = 0; i < 8; i++) {
        float v = __bfloat162float(ph[i]) + __bfloat162float(pl[i]);
        s += v * v;
    }
    float tot = warp_sum(s);
    if (lane == 0) hn[row] = -0.5f * tot;
}

// ---------------------------------------------------------------------------
// Top-96 + softmax: two-scan compaction with fallback.
// Pass 1/2 vectorized float4 (N % 4 == 0 guaranteed here: 100000 % 4 == 0),
// pass-1 histogram uses direct smem atomics (4096 bins -> rare collisions).
// ---------------------------------------------------------------------------
#define TKCAP 4096
#define TK_SMEM 81920

__device__ __forceinline__ unsigned f2o(float f) {
    unsigned u = __float_as_uint(f);
    return (u & 0x80000000u) ? ~u : (u | 0x80000000u);
}

__global__ __launch_bounds__(256)
void topk_softmax_kernel(const float* __restrict__ score, int N,
                         int* __restrict__ out_idx, float* __restrict__ out_probs)
{
    extern __shared__ unsigned char tks[];
    unsigned* hist = (unsigned*)tks;
    float* v0 = (float*)(tks + 16384);
    int*   i0 = (int*)  (tks + 32768);
    float* v1 = (float*)(tks + 49152);
    int*   i1 = (int*)  (tks + 65536);

    int row = blockIdx.x;
    const float* s = score + (size_t)row * N;
    int tid = threadIdx.x;
    int lane = tid & 31;
    int N4 = N >> 2;                      // N == 100000, divisible by 4

    __shared__ float tvals[MCTX];
    __shared__ int   tinds[MCTX];
    __shared__ int cnt_top, cnt_c, cnt_c2, cnt_eq;
    __shared__ unsigned sh_sel;
    __shared__ int sh_krem;
    __shared__ float s_max, s_sum;
    __shared__ float evals[MCTX];

    for (int b = tid; b < 4096; b += 256) hist[b] = 0;
    if (tid == 0) { cnt_top = 0; cnt_c = 0; cnt_c2 = 0; cnt_eq = 0; }
    __syncthreads();
    for (int j4 = tid; j4 < N4; j4 += 256) {
        float4 f4 = *reinterpret_cast<const float4*>(s + j4 * 4);
        atomicAdd(&hist[f2o(f4.x) >> 20], 1u);
        atomicAdd(&hist[f2o(f4.y) >> 20], 1u);
        atomicAdd(&hist[f2o(f4.z) >> 20], 1u);
        atomicAdd(&hist[f2o(f4.w) >> 20], 1u);
    }
    __syncthreads();
    if (tid == 0) {
        int cum = 0;
        unsigned bsel = 0;
        for (int b = 4095; b >= 0; b--) {
            int c = (int)hist[b];
            if (cum + c >= MCTX) { bsel = (unsigned)b; break; }
            cum += c;
        }
        sh_sel = bsel;
        sh_krem = MCTX - cum;
    }
    __syncthreads();
    unsigned sel = sh_sel;

    for (int j4 = tid; j4 < N4; j4 += 256) {
        float4 f4 = *reinterpret_cast<const float4*>(s + j4 * 4);
        float fa[4] = {f4.x, f4.y, f4.z, f4.w};
        #pragma unroll
        for (int e = 0; e < 4; e++) {
            float f = fa[e];
            unsigned b = f2o(f) >> 20;
            if (b > sel) {
                int p = atomicAdd(&cnt_top, 1);
                tvals[p] = f; tinds[p] = j4 * 4 + e;
            } else if (b == sel) {
                int p = atomicAdd(&cnt_c, 1);
                if (p < TKCAP) { v0[p] = f; i0[p] = j4 * 4 + e; }
            }
        }
    }
    __syncthreads();

    if (cnt_c <= TKCAP) {
        int nc = cnt_c;
        int krem = sh_krem;
        for (int b = tid; b < 4096; b += 256) hist[b] = 0;
        __syncthreads();
        for (int t = tid; t < nc; t += 256)
            atomicAdd(&hist[(f2o(v0[t]) >> 8) & 0xFFFu], 1);
        __syncthreads();
        if (tid == 0) {
            int cum = 0;
            unsigned bsel = 0;
            for (int b = 4095; b >= 0; b--) {
                int c = (int)hist[b];
                if (cum + c >= krem) { bsel = (unsigned)b; break; }
                cum += c;
            }
            sh_sel = bsel;
            sh_krem = krem - cum;
        }
        __syncthreads();
        unsigned sel2 = sh_sel;
        for (int t = tid; t < nc; t += 256) {
            float f = v0[t];
            unsigned m = (f2o(f) >> 8) & 0xFFFu;
            if (m > sel2) {
                int p = atomicAdd(&cnt_top, 1);
                tvals[p] = f; tinds[p] = i0[t];
            } else if (m == sel2) {
                int p = atomicAdd(&cnt_c2, 1);
                v1[p] = f; i1[p] = i0[t];
            }
        }
        __syncthreads();

        int nc2 = cnt_c2;
        int krem2 = sh_krem;
        for (int b = tid; b < 256; b += 256) hist[b] = 0;
        __syncthreads();
        for (int t = tid; t < nc2; t += 256)
            atomicAdd(&hist[f2o(v1[t]) & 0xFFu], 1);
        __syncthreads();
        if (tid == 0) {
            int cum = 0;
            unsigned bsel = 0;
            for (int b = 255; b >= 0; b--) {
                int c = (int)hist[b];
                if (cum + c >= krem2) { bsel = (unsigned)b; break; }
                cum += c;
            }
            sh_sel = bsel;
            sh_krem = krem2 - cum;
        }
        __syncthreads();
        unsigned sel3 = sh_sel;
        int need = sh_krem;
        for (int t = tid; t < nc2; t += 256) {
            float f = v1[t];
            unsigned lo = f2o(f) & 0xFFu;
            if (lo > sel3) {
                int p = atomicAdd(&cnt_top, 1);
                tvals[p] = f; tinds[p] = i1[t];
            } else if (lo == sel3) {
                int p = atomicAdd(&cnt_eq, 1);
                if (p < need) {
                    int q = atomicAdd(&cnt_top, 1);
                    tvals[q] = f; tinds[q] = i1[t];
                }
            }
        }
        __syncthreads();
    } else {
        __syncthreads();
        if (tid == 0) { cnt_top = 0; cnt_eq = 0; sh_sel = 0u; sh_krem = MCTX; }
        __syncthreads();
        int nIter = (N + 255) / 256;
        for (int shift = 24; shift >= 0; shift -= 8) {
            for (int b = tid; b < 256; b += 256) hist[b] = 0;
            __syncthreads();
            unsigned prefix = sh_sel;
            unsigned mask_hi = (shift == 24) ? 0u : (0xFFFFFFFFu << (shift + 8));
            for (int it = 0; it < nIter; it++) {
                int j = it * 256 + tid;
                bool act = false;
                unsigned bin = 0;
                if (j < N) {
                    unsigned u = f2o(s[j]);
                    act = ((u & mask_hi) == prefix);
                    bin = (u >> shift) & 255u;
                }
                int key = act ? (int)bin : (256 + lane);
                unsigned peers = __match_any_sync(0xffffffffu, key);
                int leader = __ffs(peers) - 1;
                if (act && lane == leader) atomicAdd(&hist[bin], __popc(peers));
            }
            __syncthreads();
            if (tid == 0) {
                int kr = sh_krem;
                int cum = 0, bsel = 0;
                for (int bb = 255; bb >= 0; bb--) {
                    int c = (int)hist[bb];
                    if (cum + c >= kr) { bsel = bb; break; }
                    cum += c;
                }
                sh_sel = prefix | ((unsigned)bsel << shift);
                sh_krem = kr - cum;
            }
            __syncthreads();
        }
        unsigned T = sh_sel;
        int need = sh_krem;
        for (int j = tid; j < N; j += 256) {
            float f = s[j];
            unsigned u = f2o(f);
            if (u > T) {
                int p = atomicAdd(&cnt_top, 1);
                tvals[p] = f; tinds[p] = j;
            } else if (u == T) {
                int p = atomicAdd(&cnt_eq, 1);
                if (p < need) {
                    int q = atomicAdd(&cnt_top, 1);
                    tvals[q] = f; tinds[q] = j;
                }
            }
        }
        __syncthreads();
    }

    if (tid == 0) {
        float mx = -1e30f;
        for (int m = 0; m < MCTX; m++) mx = fmaxf(mx, 2.f * tvals[m]);
        s_max = mx;
    }
    __syncthreads();
    if (tid < MCTX) evals[tid] = expf(2.f * tvals[tid] - s_max);
    __syncthreads();
    if (tid == 0) {
        float sm = 0.f;
        for (int m = 0; m < MCTX; m++) sm += evals[m];
        s_sum = sm;
    }
    __syncthreads();
    if (tid < MCTX) {
        out_probs[row * MCTX + tid] = evals[tid] / s_sum;
        out_idx[row * MCTX + tid]   = tinds[tid];
    }
}

// ---------------------------------------------------------------------------
// Warp-per-row D build from split keys
// ---------------------------------------------------------------------------
__global__ __launch_bounds__(256)
void build_d_split_warp(const bf16* __restrict__ Kh, const bf16* __restrict__ Kl,
                        const int* __restrict__ idx,
                        bf16* __restrict__ Dh, bf16* __restrict__ Dl, int nrows)
{
    int r = blockIdx.x * 8 + (threadIdx.x >> 5);
    int lane = threadIdx.x & 31;
    if (r >= nrows) return;
    int b = r / MCTX;
    int j = idx[r];
    size_t oq = (size_t)(NCAND + b) * DM + lane * 8;
    size_t oc = (size_t)j * DM + lane * 8;
    uint4 qh = *reinterpret_cast<const uint4*>(Kh + oq);
    uint4 ql = *reinterpret_cast<const uint4*>(Kl + oq);
    uint4 ch = *reinterpret_cast<const uint4*>(Kh + oc);
    uint4 cl = *reinterpret_cast<const uint4*>(Kl + oc);
    const bf16* pqh = reinterpret_cast<const bf16*>(&qh);
    const bf16* pql = reinterpret_cast<const bf16*>(&ql);
    const bf16* pch = reinterpret_cast<const bf16*>(&ch);
    const bf16* pcl = reinterpret_cast<const bf16*>(&cl);
    bf16 hv[8], lv[8];
    #pragma unroll
    for (int i = 0; i < 8; i++) {
        float kq = __bfloat162float(pqh[i]) + __bfloat162float(pql[i]);
        float kc = __bfloat162float(pch[i]) + __bfloat162float(pcl[i]);
        split2(kq - kc, hv[i], lv[i]);
    }
    *reinterpret_cast<uint4*>(Dh + (size_t)r * DM + lane * 8) = *reinterpret_cast<uint4*>(hv);
    *reinterpret_cast<uint4*>(Dl + (size_t)r * DM + lane * 8) = *reinterpret_cast<uint4*>(lv);
}

// ---------------------------------------------------------------------------
// Combine (h from split pair)
// ---------------------------------------------------------------------------
__global__ __launch_bounds__(256)
void combine_kernel(const bf16* __restrict__ Hh, const bf16* __restrict__ Hl,
                    const float* __restrict__ U,
                    const float* __restrict__ probs, const int* __restrict__ idx,
                    const float* __restrict__ cand_y, const float* __restrict__ Wy,
                    const float* __restrict__ by, const float* __restrict__ bt2,
                    float* __restrict__ xout, bf16* __restrict__ Xh, bf16* __restrict__ Xl)
{
    int b = blockIdx.x;
    int tid = threadIdx.x;
    __shared__ float p_s[MCTX];
    __shared__ float py_s[MCTX];
    __shared__ float ybar_s;
    if (tid < MCTX) {
        float p = probs[b * MCTX + tid];
        p_s[tid] = p;
        py_s[tid] = p * cand_y[idx[b * MCTX + tid]];
    }
    __syncthreads();
    if (tid == 0) {
        float yb = 0.f;
        for (int m = 0; m < MCTX; m++) yb += py_s[m];
        ybar_s = yb;
    }
    __syncthreads();
    const float* Ub = U + (size_t)b * MCTX * DM;
    float acc = 0.f;
    #pragma unroll 4
    for (int m = 0; m < MCTX; m++) acc += p_s[m] * Ub[(size_t)m * DM + tid];
    size_t ho = (size_t)(NCAND + b) * DM + tid;
    float hres = __bfloat162float(Hh[ho]) + __bfloat162float(Hl[ho]);
    float v = hres + acc + ybar_s * Wy[tid] + by[tid] + bt2[tid];
    xout[b * DM + tid] = v;
    bf16 hh, ll; split2(v, hh, ll);
    Xh[b * DM + tid] = hh;
    Xl[b * DM + tid] = ll;
}

// ---------------------------------------------------------------------------
// Head
// ---------------------------------------------------------------------------
__global__ __launch_bounds__(256)
void head_kernel(const float* __restrict__ X, const float* __restrict__ g,
                 const float* __restrict__ b, const float* __restrict__ Wh,
                 const float* __restrict__ bh, float* __restrict__ out)
{
    int r = blockIdx.x;
    int tid = threadIdx.x;
    float x = X[(size_t)r * DM + tid];
    float mu = block_sum_256(x) * (1.f / DM);
    float d = x - mu;
    float var = block_sum_256(d * d) * (1.f / DM);
    float y = d * rsqrtf(var + 1e-5f) * g[tid] + b[tid];
    float t = fmaxf(y, 0.f) * Wh[tid];
    float tot = block_sum_256(t);
    if (tid == 0) out[r] = tot + bh[0];
}

// ---------------------------------------------------------------------------
// Launcher
// ---------------------------------------------------------------------------
#define GETSYM(var, sym) cudaGetSymbolAddress((void**)&(var), sym)

extern "C" void kernel_launch(void* const* d_in, const int* in_sizes, int n_in,
                              void* d_out, int out_size)
{
    const float* x_num  = (const float*)d_in[0];
    const float* cand_x = (const float*)d_in[1];
    const float* cand_y = (const float*)d_in[2];
    int off = (n_in >= 27) ? 1 : 0;
    int i = 3 + off;
    const float* W_in = (const float*)d_in[i++]; const float* b_in = (const float*)d_in[i++];
    const float* We1  = (const float*)d_in[i++]; const float* be1  = (const float*)d_in[i++];
    const float* We2  = (const float*)d_in[i++]; const float* be2  = (const float*)d_in[i++];
    const float* g_m  = (const float*)d_in[i++]; const float* b_m  = (const float*)d_in[i++];
    const float* Ws   = (const float*)d_in[i++]; const float* bs   = (const float*)d_in[i++];
    const float* Wy   = (const float*)d_in[i++]; const float* by   = (const float*)d_in[i++];
    const float* Wt1  = (const float*)d_in[i++];
    const float* Wt2  = (const float*)d_in[i++]; const float* bt2  = (const float*)d_in[i++];
    const float* Wp1  = (const float*)d_in[i++]; const float* bp1  = (const float*)d_in[i++];
    const float* Wp2  = (const float*)d_in[i++]; const float* bp2  = (const float*)d_in[i++];
    const float* g_h  = (const float*)d_in[i++]; const float* b_h  = (const float*)d_in[i++];
    const float* Wh   = (const float*)d_in[i++]; const float* bh   = (const float*)d_in[i++];
    float* out = (float*)d_out;

    cudaFuncSetAttribute(gemm_mma, cudaFuncAttributeMaxDynamicSharedMemorySize, GEMM_SMEM);
    cudaFuncSetAttribute(topk_softmax_kernel, cudaFuncAttributeMaxDynamicSharedMemorySize, TK_SMEM);

    float *U, *score, *hnneg, *px, *probs;
    int* idxp;
    GETSYM(U, g_U); GETSYM(score, g_score);
    GETSYM(hnneg, g_hnneg); GETSYM(px, g_px);
    GETSYM(idxp, g_idx); GETSYM(probs, g_probs);

    bf16 *xh,*xl,*h0h,*h0l,*th,*tl,*lnh,*lnl,*ckh,*ckl;
    bf16 *dh,*dl,*t2h,*t2l,*pxh,*pxl,*pth,*ptl;
    GETSYM(xh, g_xh); GETSYM(xl, g_xl);
    GETSYM(h0h, g_h0h); GETSYM(h0l, g_h0l); GETSYM(th, g_th);  GETSYM(tl, g_tl);
    GETSYM(lnh, g_lnh); GETSYM(lnl, g_lnl); GETSYM(ckh, g_ckh); GETSYM(ckl, g_ckl);
    GETSYM(dh, g_dh); GETSYM(dl, g_dl); GETSYM(t2h, g_t2h); GETSYM(t2l, g_t2l);
    GETSYM(pxh, g_pxh); GETSYM(pxl, g_pxl); GETSYM(pth, g_pth); GETSYM(ptl, g_ptl);

    bf16 *winh,*winl,*we1h,*we1l,*we2h,*we2l,*wsh,*wsl,*wt1h,*wt1l,*wt2h,*wt2l,*wp1h,*wp1l,*wp2h,*wp2l;
    GETSYM(winh, g_winh); GETSYM(winl, g_winl);
    GETSYM(we1h, g_we1h); GETSYM(we1l, g_we1l);
    GETSYM(we2h, g_we2h); GETSYM(we2l, g_we2l);
    GETSYM(wsh, g_wsh);   GETSYM(wsl, g_wsl);
    GETSYM(wt1h, g_wt1h); GETSYM(wt1l, g_wt1l);
    GETSYM(wt2h, g_wt2h); GETSYM(wt2l, g_wt2l);
    GETSYM(wp1h, g_wp1h); GETSYM(wp1l, g_wp1l);
    GETSYM(wp2h, g_wp2h); GETSYM(wp2l, g_wp2l);

    // [0..2] prep
    transpose_group3<<<dim3(512, 3), 128>>>(We1, Wt1, Wp1,
                                            we1h, we1l, wt1h, wt1l, wp1h, wp1l);
    transpose_group5<<<dim3(256, 5), 128>>>(W_in, We2, Ws, Wt2, Wp2,
                                            winh, winl, we2h, we2l, wsh, wsl,
                                            wt2h, wt2l, wp2h, wp2l);
    split_x_all<<<4096, 256>>>(cand_x, x_num, xh, xl);

    const int GT = (NT + 127) / 128;     // 790

    // [3..5] combined encode (full 3-segment precision)
    gemm_mma<<<dim3(2, GT), 256, GEMM_SMEM>>>(xh, xl, winh, winl, b_in,
                                              nullptr, nullptr, nullptr,
                                              nullptr, h0h, h0l, NT, 256, 96, 8);
    gemm_mma<<<dim3(4, GT), 256, GEMM_SMEM>>>(h0h, h0l, we1h, we1l, be1,
                                              nullptr, nullptr, nullptr,
                                              nullptr, th, tl, NT, 512, 256, 1 | 8);
    gemm_mma<<<dim3(2, GT), 256, GEMM_SMEM>>>(th, tl, we2h, we2l, be2,
                                              nullptr, h0h, h0l,
                                              nullptr, h0h, h0l, NT, 256, 512, 16 | 8);
    ln_split_warp2<<<(NT + 7) / 8, 256>>>(h0h, h0l, g_m, b_m, lnh, lnl, NT);
    gemm_mma<<<dim3(2, GT), 256, GEMM_SMEM>>>(lnh, lnl, wsh, wsl, bs,
                                              nullptr, nullptr, nullptr,
                                              nullptr, ckh, ckl, NT, 256, 256, 8);
    halfnorm_neg_warp<<<(NCAND + 7) / 8, 256>>>(ckh, ckl, hnneg, NCAND);

    // similarity scores — full precision, swapped raster for L2 reuse
    gemm_mma<<<dim3(8, 782), 256, GEMM_SMEM>>>(
        ckh + (size_t)NCAND * DM, ckl + (size_t)NCAND * DM, ckh, ckl, hnneg,
        nullptr, nullptr, nullptr,
        score, nullptr, nullptr, BQ, NCAND, 256, 4 | 32);

    topk_softmax_kernel<<<BQ, 256, TK_SMEM>>>(score, NCAND, idxp, probs);
    build_d_split_warp<<<(RN + 7) / 8, 256>>>(ckh, ckl, idxp, dh, dl, RN);

    // value MLP — 2-segment mode (post-selection)
    gemm_mma<<<dim3(4, 768), 256, GEMM_SMEM>>>(dh, dl, wt1h, wt1l, nullptr,
                                               nullptr, nullptr, nullptr,
                                               nullptr, t2h, t2l, RN, 512, 256, 1 | 8 | 64);
    gemm_mma<<<dim3(2, 768), 256, GEMM_SMEM>>>(t2h, t2l, wt2h, wt2l, nullptr,
                                               nullptr, nullptr, nullptr,
                                               U, nullptr, nullptr, RN, 256, 512, 4 | 64);

    combine_kernel<<<BQ, 256>>>(h0h, h0l, U, probs, idxp, cand_y, Wy, by, bt2,
                                px, pxh, pxl);

    // predictor + head (full precision)
    gemm_mma<<<dim3(4, 8), 256, GEMM_SMEM>>>(pxh, pxl, wp1h, wp1l, bp1,
                                             nullptr, nullptr, nullptr,
                                             nullptr, pth, ptl, BQ, 512, 256, 1 | 8);
    gemm_mma<<<dim3(2, 8), 256, GEMM_SMEM>>>(pth, ptl, wp2h, wp2l, bp2,
                                             px, nullptr, nullptr,
                                             px, nullptr, nullptr, BQ, 256, 512, 2 | 4);
    head_kernel<<<BQ, 256>>>(px, g_h, b_h, Wh, bh, out);

    (void)in_sizes; (void)out_size;
}

// round 15
// speedup vs baseline: 1.4485x; 1.0375x over previous
#include <cuda_runtime.h>
#include <cuda_bf16.h>
#include <math.h>
#include <stdint.h>

// ---------------------------------------------------------------------------
// Problem constants
// ---------------------------------------------------------------------------
#define NCAND 100000
#define BQ    1024
#define NT    (NCAND + BQ)
#define DM    256
#define DH    512
#define NNUM  96
#define MCTX  96
#define RN    (BQ * MCTX)

typedef __nv_bfloat16 bf16;

// ---------------------------------------------------------------------------
// Device scratch
// ---------------------------------------------------------------------------
__device__ float g_score[(size_t)BQ * NCAND];
__device__ float g_hnneg[NCAND];
__device__ float g_px [BQ * DM];
__device__ float g_Us [BQ * DM];            // (S @ Wt2) f32, small
__device__ int   g_idx [BQ * MCTX];
__device__ float g_probs[BQ * MCTX];

__device__ bf16 g_xh [(size_t)NT * 96],  g_xl [(size_t)NT * 96];
__device__ bf16 g_h0h[(size_t)NT * DM],  g_h0l[(size_t)NT * DM];
__device__ bf16 g_th [(size_t)NT * DH],  g_tl [(size_t)NT * DH];
__device__ bf16 g_lnh[(size_t)NT * DM],  g_lnl[(size_t)NT * DM];
__device__ bf16 g_ckh[(size_t)NT * DM],  g_ckl[(size_t)NT * DM];
__device__ bf16 g_dh [(size_t)RN * DM],  g_dl [(size_t)RN * DM];
__device__ bf16 g_t2h[(size_t)RN * DH],  g_t2l[(size_t)RN * DH];
__device__ bf16 g_sh [BQ * DH], g_sl [BQ * DH];   // weighted-sum S split
__device__ bf16 g_pxh[BQ * DM], g_pxl[BQ * DM];
__device__ bf16 g_pth[BQ * DH], g_ptl[BQ * DH];

__device__ bf16 g_winh[256 * 96],  g_winl[256 * 96];
__device__ bf16 g_we1h[512 * 256], g_we1l[512 * 256];
__device__ bf16 g_we2h[256 * 512], g_we2l[256 * 512];
__device__ bf16 g_wsh [256 * 256], g_wsl [256 * 256];
__device__ bf16 g_wt1h[512 * 256], g_wt1l[512 * 256];
__device__ bf16 g_wt2h[256 * 512], g_wt2l[256 * 512];
__device__ bf16 g_wp1h[512 * 256], g_wp1l[512 * 256];
__device__ bf16 g_wp2h[256 * 512], g_wp2l[256 * 512];

// ---------------------------------------------------------------------------
// Helpers
// ---------------------------------------------------------------------------
__device__ __forceinline__ uint32_t smem_u32(const void* p) {
    uint32_t a;
    asm("{ .reg .u64 t; cvta.to.shared.u64 t, %1; cvt.u32.u64 %0, t; }" : "=r"(a) : "l"(p));
    return a;
}

__device__ __forceinline__ void cp16(uint32_t dst, const void* src, bool valid) {
    int sz = valid ? 16 : 0;
    asm volatile("cp.async.cg.shared.global [%0], [%1], 16, %2;"
                 :: "r"(dst), "l"(src), "r"(sz));
}
#define CP_COMMIT() asm volatile("cp.async.commit_group;")
#define CP_WAIT(n)  asm volatile("cp.async.wait_group %0;" :: "n"(n))

__device__ __forceinline__ void ldsm4(uint32_t addr, uint32_t& r0, uint32_t& r1,
                                      uint32_t& r2, uint32_t& r3) {
    asm volatile("ldmatrix.sync.aligned.m8n8.x4.shared.b16 {%0,%1,%2,%3}, [%4];"
                 : "=r"(r0), "=r"(r1), "=r"(r2), "=r"(r3) : "r"(addr));
}

__device__ __forceinline__ void mma16816(float* c, const uint32_t* a, const uint32_t* b) {
    asm volatile(
        "mma.sync.aligned.m16n8k16.row.col.f32.bf16.bf16.f32 "
        "{%0,%1,%2,%3}, {%4,%5,%6,%7}, {%8,%9}, {%0,%1,%2,%3};"
        : "+f"(c[0]), "+f"(c[1]), "+f"(c[2]), "+f"(c[3])
        : "r"(a[0]), "r"(a[1]), "r"(a[2]), "r"(a[3]), "r"(b[0]), "r"(b[1]));
}

__device__ __forceinline__ float block_sum_256(float v) {
    __shared__ float sh[8];
    int lane = threadIdx.x & 31, w = threadIdx.x >> 5;
    #pragma unroll
    for (int o = 16; o > 0; o >>= 1) v += __shfl_xor_sync(0xffffffffu, v, o);
    __syncthreads();
    if (lane == 0) sh[w] = v;
    __syncthreads();
    float t = sh[0];
    #pragma unroll
    for (int i = 1; i < 8; i++) t += sh[i];
    return t;
}

__device__ __forceinline__ float warp_sum(float v) {
    #pragma unroll
    for (int o = 16; o > 0; o >>= 1) v += __shfl_xor_sync(0xffffffffu, v, o);
    return v;
}

__device__ __forceinline__ void split2(float v, bf16& h, bf16& l) {
    h = __float2bfloat16(v);
    l = __float2bfloat16(v - __bfloat162float(h));
}

// ---------------------------------------------------------------------------
// gemm_mma: FROZEN core (issue -> wait -> barrier -> compute).
// flags: 1 relu, 2 +res(f32), 4 write f32 C, 8 write split (Ch,Cl),
//        16 +res split (Rh+Rl), 32 swap block-index mapping, 64 two-segment
// ---------------------------------------------------------------------------
#define LDA 40
#define STG_ELEM (128 * LDA)
#define STAGE_BYTES (2 * STG_ELEM * 2)
#define NSTAGE 5
#define GEMM_SMEM (NSTAGE * STAGE_BYTES)

__global__ __launch_bounds__(256, 2)
void gemm_mma(const bf16* __restrict__ Ah, const bf16* __restrict__ Al,
              const bf16* __restrict__ Bh, const bf16* __restrict__ Bl,
              const float* __restrict__ bias, const float* __restrict__ res,
              const bf16* __restrict__ Rh, const bf16* __restrict__ Rl,
              float* __restrict__ C, bf16* __restrict__ Ch, bf16* __restrict__ Cl,
              int M, int N, int Kp, int flags)
{
    extern __shared__ __align__(16) bf16 sdyn[];
    __shared__ float sbias[128];

    const int tid  = threadIdx.x;
    const int lane = tid & 31;
    const int wid  = tid >> 5;
    const int wm   = wid & 3;
    const int wn   = wid >> 2;
    const int bm   = ((flags & 32) ? blockIdx.x : blockIdx.y) * 128;
    const int bn   = ((flags & 32) ? blockIdx.y : blockIdx.x) * 128;

    if (tid < 128) {
        int col = bn + tid;
        sbias[tid] = (bias != nullptr && col < N) ? bias[col] : 0.f;
    }

    const uint32_t sBase = smem_u32(sdyn);

    const bf16* segA[3] = {Ah, Ah, Al};
    const bf16* segB[3] = {Bh, Bl, Bh};
    if (flags & 64) { segA[1] = Al; segB[1] = Bh; }
    const int nseg = (flags & 64) ? 2 : 3;
    const int nk = Kp >> 5;
    const int NC = nseg * nk;

    float acc[2][8][4];
    #pragma unroll
    for (int t = 0; t < 2; t++)
        #pragma unroll
        for (int j = 0; j < 8; j++)
            #pragma unroll
            for (int e = 0; e < 4; e++) acc[t][j][e] = 0.f;

    auto issue = [&](int c, int st) {
        int seg = c / nk;
        int k0  = (c - seg * nk) << 5;
        const bf16* Ap = segA[seg];
        const bf16* Bp = segB[seg];
        uint32_t stA = sBase + (uint32_t)(st * STAGE_BYTES);
        uint32_t stB = stA + STG_ELEM * 2;
        #pragma unroll
        for (int h = 0; h < 2; h++) {
            int q   = tid + h * 256;
            int row = q >> 2;
            int sg  = q & 3;
            uint32_t off = (uint32_t)(row * 80 + sg * 16);
            int ar = bm + row; bool av = ar < M; if (!av) ar = 0;
            cp16(stA + off, Ap + (size_t)ar * Kp + k0 + sg * 8, av);
            int br = bn + row; bool bv = br < N; if (!bv) br = 0;
            cp16(stB + off, Bp + (size_t)br * Kp + k0 + sg * 8, bv);
        }
        CP_COMMIT();
    };

    issue(0, 0);
    issue(1, 1);
    issue(2, 2);
    int st_w = 3, st_r = 0;
    for (int c = 0; c < NC; ++c) {
        if (c + 3 < NC) {
            issue(c + 3, st_w);
            if (++st_w == NSTAGE) st_w = 0;
        } else {
            CP_COMMIT();
        }
        CP_WAIT(3);
        __syncthreads();

        uint32_t stA = sBase + (uint32_t)(st_r * STAGE_BYTES);
        uint32_t stB = stA + STG_ELEM * 2;
        if (++st_r == NSTAGE) st_r = 0;
        uint32_t aBase = stA + (uint32_t)((wm * 32) * 80);
        uint32_t bBase = stB + (uint32_t)((wn * 64) * 80);

        #pragma unroll
        for (int ks = 0; ks < 32; ks += 16) {
            uint32_t a[2][4];
            #pragma unroll
            for (int t = 0; t < 2; t++) {
                uint32_t addr = aBase + (uint32_t)((t * 16 + (lane & 15)) * 80
                                                   + (ks + (lane >> 4) * 8) * 2);
                ldsm4(addr, a[t][0], a[t][1], a[t][2], a[t][3]);
            }
            uint32_t b[8][2];
            #pragma unroll
            for (int jp = 0; jp < 4; jp++) {
                int grp = lane >> 3;
                int row = jp * 16 + (grp >> 1) * 8 + (lane & 7);
                int kof = (grp & 1) * 8;
                uint32_t addr = bBase + (uint32_t)(row * 80 + (ks + kof) * 2);
                ldsm4(addr, b[2 * jp][0], b[2 * jp][1], b[2 * jp + 1][0], b[2 * jp + 1][1]);
            }
            #pragma unroll
            for (int t = 0; t < 2; t++)
                #pragma unroll
                for (int j = 0; j < 8; j++)
                    mma16816(acc[t][j], a[t], b[j]);
        }
    }

    // ---- epilogue ----
    int colb = (lane & 3) * 2;
    #pragma unroll
    for (int t = 0; t < 2; t++) {
        int row0 = bm + wm * 32 + t * 16 + (lane >> 2);
        #pragma unroll
        for (int j = 0; j < 8; j++) {
            int col = bn + wn * 64 + j * 8 + colb;
            if (col >= N) continue;
            #pragma unroll
            for (int half = 0; half < 2; half++) {
                int rr = row0 + half * 8;
                if (rr >= M) continue;
                float v0 = acc[t][j][half * 2 + 0];
                float v1 = acc[t][j][half * 2 + 1];
                int cl = col - bn;
                v0 += sbias[cl]; v1 += sbias[cl + 1];
                if (flags & 1) { v0 = fmaxf(v0, 0.f); v1 = fmaxf(v1, 0.f); }
                size_t o = (size_t)rr * N + col;
                if (flags & 2) {
                    float2 r2 = *reinterpret_cast<const float2*>(res + o);
                    v0 += r2.x; v1 += r2.y;
                }
                if (flags & 16) {
                    __nv_bfloat162 rh = *reinterpret_cast<const __nv_bfloat162*>(Rh + o);
                    __nv_bfloat162 rl = *reinterpret_cast<const __nv_bfloat162*>(Rl + o);
                    v0 += __bfloat162float(rh.x) + __bfloat162float(rl.x);
                    v1 += __bfloat162float(rh.y) + __bfloat162float(rl.y);
                }
                if (flags & 4) {
                    *reinterpret_cast<float2*>(C + o) = make_float2(v0, v1);
                }
                if (flags & 8) {
                    bf16 h0, l0, h1, l1;
                    split2(v0, h0, l0); split2(v1, h1, l1);
                    *reinterpret_cast<__nv_bfloat162*>(Ch + o) = __nv_bfloat162(h0, h1);
                    *reinterpret_cast<__nv_bfloat162*>(Cl + o) = __nv_bfloat162(l0, l1);
                }
            }
        }
    }
}

// ---------------------------------------------------------------------------
// Grouped weight prep
// ---------------------------------------------------------------------------
__global__ void transpose_group3(const float* __restrict__ W0, const float* __restrict__ W1,
                                 const float* __restrict__ W2,
                                 bf16* __restrict__ T0h, bf16* __restrict__ T0l,
                                 bf16* __restrict__ T1h, bf16* __restrict__ T1l,
                                 bf16* __restrict__ T2h, bf16* __restrict__ T2l)
{
    int w = blockIdx.y;
    const float* W = (w == 0) ? W0 : (w == 1) ? W1 : W2;
    bf16* Th = (w == 0) ? T0h : (w == 1) ? T1h : T2h;
    bf16* Tl = (w == 0) ? T0l : (w == 1) ? T1l : T2l;
    int n = blockIdx.x;
    for (int k = threadIdx.x; k < 256; k += 128) {
        float v = W[(size_t)k * 512 + n];
        bf16 h, l; split2(v, h, l);
        Th[(size_t)n * 256 + k] = h;
        Tl[(size_t)n * 256 + k] = l;
    }
}

__global__ void transpose_group5(const float* __restrict__ Win, const float* __restrict__ We2,
                                 const float* __restrict__ Ws,  const float* __restrict__ Wt2,
                                 const float* __restrict__ Wp2,
                                 bf16* __restrict__ T0h, bf16* __restrict__ T0l,
                                 bf16* __restrict__ T1h, bf16* __restrict__ T1l,
                                 bf16* __restrict__ T2h, bf16* __restrict__ T2l,
                                 bf16* __restrict__ T3h, bf16* __restrict__ T3l,
                                 bf16* __restrict__ T4h, bf16* __restrict__ T4l)
{
    int w = blockIdx.y;
    const float* Wt[5] = {Win, We2, Ws, Wt2, Wp2};
    bf16* Tht[5] = {T0h, T1h, T2h, T3h, T4h};
    bf16* Tlt[5] = {T0l, T1l, T2l, T3l, T4l};
    const int Ks [5] = {96, 512, 256, 512, 512};
    const int Kps[5] = {96, 512, 256, 512, 512};
    const float* W = Wt[w];
    bf16* Th = Tht[w];
    bf16* Tl = Tlt[w];
    int K = Ks[w], Kp = Kps[w];
    int n = blockIdx.x;
    for (int k = threadIdx.x; k < Kp; k += 128) {
        float v = (k < K) ? W[(size_t)k * 256 + n] : 0.f;
        bf16 h, l; split2(v, h, l);
        Th[(size_t)n * Kp + k] = h;
        Tl[(size_t)n * Kp + k] = l;
    }
}

__global__ __launch_bounds__(256)
void split_x_all(const float* __restrict__ cand, const float* __restrict__ q,
                 bf16* __restrict__ Xh, bf16* __restrict__ Xl)
{
    size_t total = (size_t)NT * NNUM;
    for (size_t e = (size_t)blockIdx.x * 256 + threadIdx.x; e < total;
         e += (size_t)gridDim.x * 256) {
        size_t r = e / NNUM;
        int t = (int)(e - r * NNUM);
        float v = (r < NCAND) ? cand[r * NNUM + t] : q[(r - NCAND) * NNUM + t];
        bf16 h, l; split2(v, h, l);
        Xh[e] = h;
        Xl[e] = l;
    }
}

// ---------------------------------------------------------------------------
// Warp-per-row LayerNorm from SPLIT input -> split output ; warp half-norm
// ---------------------------------------------------------------------------
__global__ __launch_bounds__(256)
void ln_split_warp2(const bf16* __restrict__ Hh, const bf16* __restrict__ Hl,
                    const float* __restrict__ g, const float* __restrict__ b,
                    bf16* __restrict__ Yh, bf16* __restrict__ Yl, int nrows)
{
    int row = blockIdx.x * 8 + (threadIdx.x >> 5);
    int lane = threadIdx.x & 31;
    if (row >= nrows) return;
    uint4 uh = *reinterpret_cast<const uint4*>(Hh + (size_t)row * DM + lane * 8);
    uint4 ul = *reinterpret_cast<const uint4*>(Hl + (size_t)row * DM + lane * 8);
    const bf16* ph = reinterpret_cast<const bf16*>(&uh);
    const bf16* pl = reinterpret_cast<const bf16*>(&ul);
    float fv[8];
    float s = 0.f;
    #pragma unroll
    for (int i = 0; i < 8; i++) {
        fv[i] = __bfloat162float(ph[i]) + __bfloat162float(pl[i]);
        s += fv[i];
    }
    float mu = warp_sum(s) * (1.f / DM);
    float vs = 0.f;
    #pragma unroll
    for (int i = 0; i < 8; i++) { fv[i] -= mu; vs += fv[i] * fv[i]; }
    float rstd = rsqrtf(warp_sum(vs) * (1.f / DM) + 1e-5f);
    float4 g0 = *reinterpret_cast<const float4*>(g + lane * 8);
    float4 g1 = *reinterpret_cast<const float4*>(g + lane * 8 + 4);
    float4 b0 = *reinterpret_cast<const float4*>(b + lane * 8);
    float4 b1 = *reinterpret_cast<const float4*>(b + lane * 8 + 4);
    float gr[8] = {g0.x, g0.y, g0.z, g0.w, g1.x, g1.y, g1.z, g1.w};
    float br[8] = {b0.x, b0.y, b0.z, b0.w, b1.x, b1.y, b1.z, b1.w};
    bf16 hv[8], lv[8];
    #pragma unroll
    for (int i = 0; i < 8; i++) {
        float y = fv[i] * rstd * gr[i] + br[i];
        split2(y, hv[i], lv[i]);
    }
    *reinterpret_cast<uint4*>(Yh + (size_t)row * DM + lane * 8) = *reinterpret_cast<uint4*>(hv);
    *reinterpret_cast<uint4*>(Yl + (size_t)row * DM + lane * 8) = *reinterpret_cast<uint4*>(lv);
}

__global__ __launch_bounds__(256)
void halfnorm_neg_warp(const bf16* __restrict__ Kh, const bf16* __restrict__ Kl,
                       float* __restrict__ hn, int nrows)
{
    int row = blockIdx.x * 8 + (threadIdx.x >> 5);
    int lane = threadIdx.x & 31;
    if (row >= nrows) return;
    uint4 uh = *reinterpret_cast<const uint4*>(Kh + (size_t)row * DM + lane * 8);
    uint4 ul = *reinterpret_cast<const uint4*>(Kl + (size_t)row * DM + lane * 8);
    const bf16* ph = reinterpret_cast<const bf16*>(&uh);
    const bf16* pl = reinterpret_cast<const bf16*>(&ul);
    float s = 0.f;
    #pragma unroll
    for (int i = 0; i < 8; i++) {
        float v = __bfloat162float(ph[i]) + __bfloat162float(pl[i]);
        s += v * v;
    }
    float tot = warp_sum(s);
    if (lane == 0) hn[row] = -0.5f * tot;
}

// ---------------------------------------------------------------------------
// Top-96 + softmax: two-scan compaction with fallback (round-14, proven).
// ---------------------------------------------------------------------------
#define TKCAP 4096
#define TK_SMEM 81920

__device__ __forceinline__ unsigned f2o(float f) {
    unsigned u = __float_as_uint(f);
    return (u & 0x80000000u) ? ~u : (u | 0x80000000u);
}

__global__ __launch_bounds__(256)
void topk_softmax_kernel(const float* __restrict__ score, int N,
                         int* __restrict__ out_idx, float* __restrict__ out_probs)
{
    extern __shared__ unsigned char tks[];
    unsigned* hist = (unsigned*)tks;
    float* v0 = (float*)(tks + 16384);
    int*   i0 = (int*)  (tks + 32768);
    float* v1 = (float*)(tks + 49152);
    int*   i1 = (int*)  (tks + 65536);

    int row = blockIdx.x;
    const float* s = score + (size_t)row * N;
    int tid = threadIdx.x;
    int lane = tid & 31;
    int N4 = N >> 2;

    __shared__ float tvals[MCTX];
    __shared__ int   tinds[MCTX];
    __shared__ int cnt_top, cnt_c, cnt_c2, cnt_eq;
    __shared__ unsigned sh_sel;
    __shared__ int sh_krem;
    __shared__ float s_max, s_sum;
    __shared__ float evals[MCTX];

    for (int b = tid; b < 4096; b += 256) hist[b] = 0;
    if (tid == 0) { cnt_top = 0; cnt_c = 0; cnt_c2 = 0; cnt_eq = 0; }
    __syncthreads();
    for (int j4 = tid; j4 < N4; j4 += 256) {
        float4 f4 = *reinterpret_cast<const float4*>(s + j4 * 4);
        atomicAdd(&hist[f2o(f4.x) >> 20], 1u);
        atomicAdd(&hist[f2o(f4.y) >> 20], 1u);
        atomicAdd(&hist[f2o(f4.z) >> 20], 1u);
        atomicAdd(&hist[f2o(f4.w) >> 20], 1u);
    }
    __syncthreads();
    if (tid == 0) {
        int cum = 0;
        unsigned bsel = 0;
        for (int b = 4095; b >= 0; b--) {
            int c = (int)hist[b];
            if (cum + c >= MCTX) { bsel = (unsigned)b; break; }
            cum += c;
        }
        sh_sel = bsel;
        sh_krem = MCTX - cum;
    }
    __syncthreads();
    unsigned sel = sh_sel;

    for (int j4 = tid; j4 < N4; j4 += 256) {
        float4 f4 = *reinterpret_cast<const float4*>(s + j4 * 4);
        float fa[4] = {f4.x, f4.y, f4.z, f4.w};
        #pragma unroll
        for (int e = 0; e < 4; e++) {
            float f = fa[e];
            unsigned b = f2o(f) >> 20;
            if (b > sel) {
                int p = atomicAdd(&cnt_top, 1);
                tvals[p] = f; tinds[p] = j4 * 4 + e;
            } else if (b == sel) {
                int p = atomicAdd(&cnt_c, 1);
                if (p < TKCAP) { v0[p] = f; i0[p] = j4 * 4 + e; }
            }
        }
    }
    __syncthreads();

    if (cnt_c <= TKCAP) {
        int nc = cnt_c;
        int krem = sh_krem;
        for (int b = tid; b < 4096; b += 256) hist[b] = 0;
        __syncthreads();
        for (int t = tid; t < nc; t += 256)
            atomicAdd(&hist[(f2o(v0[t]) >> 8) & 0xFFFu], 1);
        __syncthreads();
        if (tid == 0) {
            int cum = 0;
            unsigned bsel = 0;
            for (int b = 4095; b >= 0; b--) {
                int c = (int)hist[b];
                if (cum + c >= krem) { bsel = (unsigned)b; break; }
                cum += c;
            }
            sh_sel = bsel;
            sh_krem = krem - cum;
        }
        __syncthreads();
        unsigned sel2 = sh_sel;
        for (int t = tid; t < nc; t += 256) {
            float f = v0[t];
            unsigned m = (f2o(f) >> 8) & 0xFFFu;
            if (m > sel2) {
                int p = atomicAdd(&cnt_top, 1);
                tvals[p] = f; tinds[p] = i0[t];
            } else if (m == sel2) {
                int p = atomicAdd(&cnt_c2, 1);
                v1[p] = f; i1[p] = i0[t];
            }
        }
        __syncthreads();

        int nc2 = cnt_c2;
        int krem2 = sh_krem;
        for (int b = tid; b < 256; b += 256) hist[b] = 0;
        __syncthreads();
        for (int t = tid; t < nc2; t += 256)
            atomicAdd(&hist[f2o(v1[t]) & 0xFFu], 1);
        __syncthreads();
        if (tid == 0) {
            int cum = 0;
            unsigned bsel = 0;
            for (int b = 255; b >= 0; b--) {
                int c = (int)hist[b];
                if (cum + c >= krem2) { bsel = (unsigned)b; break; }
                cum += c;
            }
            sh_sel = bsel;
            sh_krem = krem2 - cum;
        }
        __syncthreads();
        unsigned sel3 = sh_sel;
        int need = sh_krem;
        for (int t = tid; t < nc2; t += 256) {
            float f = v1[t];
            unsigned lo = f2o(f) & 0xFFu;
            if (lo > sel3) {
                int p = atomicAdd(&cnt_top, 1);
                tvals[p] = f; tinds[p] = i1[t];
            } else if (lo == sel3) {
                int p = atomicAdd(&cnt_eq, 1);
                if (p < need) {
                    int q = atomicAdd(&cnt_top, 1);
                    tvals[q] = f; tinds[q] = i1[t];
                }
            }
        }
        __syncthreads();
    } else {
        __syncthreads();
        if (tid == 0) { cnt_top = 0; cnt_eq = 0; sh_sel = 0u; sh_krem = MCTX; }
        __syncthreads();
        int nIter = (N + 255) / 256;
        for (int shift = 24; shift >= 0; shift -= 8) {
            for (int b = tid; b < 256; b += 256) hist[b] = 0;
            __syncthreads();
            unsigned prefix = sh_sel;
            unsigned mask_hi = (shift == 24) ? 0u : (0xFFFFFFFFu << (shift + 8));
            for (int it = 0; it < nIter; it++) {
                int j = it * 256 + tid;
                bool act = false;
                unsigned bin = 0;
                if (j < N) {
                    unsigned u = f2o(s[j]);
                    act = ((u & mask_hi) == prefix);
                    bin = (u >> shift) & 255u;
                }
                int key = act ? (int)bin : (256 + lane);
                unsigned peers = __match_any_sync(0xffffffffu, key);
                int leader = __ffs(peers) - 1;
                if (act && lane == leader) atomicAdd(&hist[bin], __popc(peers));
            }
            __syncthreads();
            if (tid == 0) {
                int kr = sh_krem;
                int cum = 0, bsel = 0;
                for (int bb = 255; bb >= 0; bb--) {
                    int c = (int)hist[bb];
                    if (cum + c >= kr) { bsel = bb; break; }
                    cum += c;
                }
                sh_sel = prefix | ((unsigned)bsel << shift);
                sh_krem = kr - cum;
            }
            __syncthreads();
        }
        unsigned T = sh_sel;
        int need = sh_krem;
        for (int j = tid; j < N; j += 256) {
            float f = s[j];
            unsigned u = f2o(f);
            if (u > T) {
                int p = atomicAdd(&cnt_top, 1);
                tvals[p] = f; tinds[p] = j;
            } else if (u == T) {
                int p = atomicAdd(&cnt_eq, 1);
                if (p < need) {
                    int q = atomicAdd(&cnt_top, 1);
                    tvals[q] = f; tinds[q] = j;
                }
            }
        }
        __syncthreads();
    }

    if (tid == 0) {
        float mx = -1e30f;
        for (int m = 0; m < MCTX; m++) mx = fmaxf(mx, 2.f * tvals[m]);
        s_max = mx;
    }
    __syncthreads();
    if (tid < MCTX) evals[tid] = expf(2.f * tvals[tid] - s_max);
    __syncthreads();
    if (tid == 0) {
        float sm = 0.f;
        for (int m = 0; m < MCTX; m++) sm += evals[m];
        s_sum = sm;
    }
    __syncthreads();
    if (tid < MCTX) {
        out_probs[row * MCTX + tid] = evals[tid] / s_sum;
        out_idx[row * MCTX + tid]   = tinds[tid];
    }
}

// ---------------------------------------------------------------------------
// Warp-per-row D build from split keys
// ---------------------------------------------------------------------------
__global__ __launch_bounds__(256)
void build_d_split_warp(const bf16* __restrict__ Kh, const bf16* __restrict__ Kl,
                        const int* __restrict__ idx,
                        bf16* __restrict__ Dh, bf16* __restrict__ Dl, int nrows)
{
    int r = blockIdx.x * 8 + (threadIdx.x >> 5);
    int lane = threadIdx.x & 31;
    if (r >= nrows) return;
    int b = r / MCTX;
    int j = idx[r];
    size_t oq = (size_t)(NCAND + b) * DM + lane * 8;
    size_t oc = (size_t)j * DM + lane * 8;
    uint4 qh = *reinterpret_cast<const uint4*>(Kh + oq);
    uint4 ql = *reinterpret_cast<const uint4*>(Kl + oq);
    uint4 ch = *reinterpret_cast<const uint4*>(Kh + oc);
    uint4 cl = *reinterpret_cast<const uint4*>(Kl + oc);
    const bf16* pqh = reinterpret_cast<const bf16*>(&qh);
    const bf16* pql = reinterpret_cast<const bf16*>(&ql);
    const bf16* pch = reinterpret_cast<const bf16*>(&ch);
    const bf16* pcl = reinterpret_cast<const bf16*>(&cl);
    bf16 hv[8], lv[8];
    #pragma unroll
    for (int i = 0; i < 8; i++) {
        float kq = __bfloat162float(pqh[i]) + __bfloat162float(pql[i]);
        float kc = __bfloat162float(pch[i]) + __bfloat162float(pcl[i]);
        split2(kq - kc, hv[i], lv[i]);
    }
    *reinterpret_cast<uint4*>(Dh + (size_t)r * DM + lane * 8) = *reinterpret_cast<uint4*>(hv);
    *reinterpret_cast<uint4*>(Dl + (size_t)r * DM + lane * 8) = *reinterpret_cast<uint4*>(lv);
}

// ---------------------------------------------------------------------------
// Weighted sum over contexts: S_b[d] = sum_m p[b,m] * (t2h+t2l)[b*96+m, d]
// One CTA (256 thr) per query b; each thread owns 2 of the 512 columns.
// Exact reassociation of (p @ relu(D Wt1)) before @Wt2 (linearity).
// ---------------------------------------------------------------------------
__global__ __launch_bounds__(256)
void weighted_sum_t2(const bf16* __restrict__ T2h, const bf16* __restrict__ T2l,
                     const float* __restrict__ probs,
                     bf16* __restrict__ Sh, bf16* __restrict__ Sl)
{
    int b = blockIdx.x;
    int tid = threadIdx.x;
    __shared__ float p_s[MCTX];
    if (tid < MCTX) p_s[tid] = probs[b * MCTX + tid];
    __syncthreads();
    float acc0 = 0.f, acc1 = 0.f;
    const size_t base = (size_t)b * MCTX * DH;
    #pragma unroll 4
    for (int m = 0; m < MCTX; m++) {
        size_t ro = base + (size_t)m * DH;
        float p = p_s[m];
        acc0 += p * (__bfloat162float(T2h[ro + tid])
                   + __bfloat162float(T2l[ro + tid]));
        acc1 += p * (__bfloat162float(T2h[ro + 256 + tid])
                   + __bfloat162float(T2l[ro + 256 + tid]));
    }
    bf16 h0, l0, h1, l1;
    split2(acc0, h0, l0);
    split2(acc1, h1, l1);
    Sh[(size_t)b * DH + tid]       = h0;
    Sl[(size_t)b * DH + tid]       = l0;
    Sh[(size_t)b * DH + 256 + tid] = h1;
    Sl[(size_t)b * DH + 256 + tid] = l1;
}

// ---------------------------------------------------------------------------
// Combine: x = h + Us + ybar*Wy + by + bt2  (Us = (S@Wt2) f32, small)
// ---------------------------------------------------------------------------
__global__ __launch_bounds__(256)
void combine_kernel(const bf16* __restrict__ Hh, const bf16* __restrict__ Hl,
                    const float* __restrict__ Us,
                    const float* __restrict__ probs, const int* __restrict__ idx,
                    const float* __restrict__ cand_y, const float* __restrict__ Wy,
                    const float* __restrict__ by, const float* __restrict__ bt2,
                    float* __restrict__ xout, bf16* __restrict__ Xh, bf16* __restrict__ Xl)
{
    int b = blockIdx.x;
    int tid = threadIdx.x;
    __shared__ float py_s[MCTX];
    __shared__ float ybar_s;
    if (tid < MCTX)
        py_s[tid] = probs[b * MCTX + tid] * cand_y[idx[b * MCTX + tid]];
    __syncthreads();
    if (tid == 0) {
        float yb = 0.f;
        for (int m = 0; m < MCTX; m++) yb += py_s[m];
        ybar_s = yb;
    }
    __syncthreads();
    size_t ho = (size_t)(NCAND + b) * DM + tid;
    float hres = __bfloat162float(Hh[ho]) + __bfloat162float(Hl[ho]);
    float v = hres + Us[b * DM + tid] + ybar_s * Wy[tid] + by[tid] + bt2[tid];
    xout[b * DM + tid] = v;
    bf16 hh, ll; split2(v, hh, ll);
    Xh[b * DM + tid] = hh;
    Xl[b * DM + tid] = ll;
}

// ---------------------------------------------------------------------------
// Head
// ---------------------------------------------------------------------------
__global__ __launch_bounds__(256)
void head_kernel(const float* __restrict__ X, const float* __restrict__ g,
                 const float* __restrict__ b, const float* __restrict__ Wh,
                 const float* __restrict__ bh, float* __restrict__ out)
{
    int r = blockIdx.x;
    int tid = threadIdx.x;
    float x = X[(size_t)r * DM + tid];
    float mu = block_sum_256(x) * (1.f / DM);
    float d = x - mu;
    float var = block_sum_256(d * d) * (1.f / DM);
    float y = d * rsqrtf(var + 1e-5f) * g[tid] + b[tid];
    float t = fmaxf(y, 0.f) * Wh[tid];
    float tot = block_sum_256(t);
    if (tid == 0) out[r] = tot + bh[0];
}

// ---------------------------------------------------------------------------
// Launcher
// ---------------------------------------------------------------------------
#define GETSYM(var, sym) cudaGetSymbolAddress((void**)&(var), sym)

extern "C" void kernel_launch(void* const* d_in, const int* in_sizes, int n_in,
                              void* d_out, int out_size)
{
    const float* x_num  = (const float*)d_in[0];
    const float* cand_x = (const float*)d_in[1];
    const float* cand_y = (const float*)d_in[2];
    int off = (n_in >= 27) ? 1 : 0;
    int i = 3 + off;
    const float* W_in = (const float*)d_in[i++]; const float* b_in = (const float*)d_in[i++];
    const float* We1  = (const float*)d_in[i++]; const float* be1  = (const float*)d_in[i++];
    const float* We2  = (const float*)d_in[i++]; const float* be2  = (const float*)d_in[i++];
    const float* g_m  = (const float*)d_in[i++]; const float* b_m  = (const float*)d_in[i++];
    const float* Ws   = (const float*)d_in[i++]; const float* bs   = (const float*)d_in[i++];
    const float* Wy   = (const float*)d_in[i++]; const float* by   = (const float*)d_in[i++];
    const float* Wt1  = (const float*)d_in[i++];
    const float* Wt2  = (const float*)d_in[i++]; const float* bt2  = (const float*)d_in[i++];
    const float* Wp1  = (const float*)d_in[i++]; const float* bp1  = (const float*)d_in[i++];
    const float* Wp2  = (const float*)d_in[i++]; const float* bp2  = (const float*)d_in[i++];
    const float* g_h  = (const float*)d_in[i++]; const float* b_h  = (const float*)d_in[i++];
    const float* Wh   = (const float*)d_in[i++]; const float* bh   = (const float*)d_in[i++];
    float* out = (float*)d_out;

    cudaFuncSetAttribute(gemm_mma, cudaFuncAttributeMaxDynamicSharedMemorySize, GEMM_SMEM);
    cudaFuncSetAttribute(topk_softmax_kernel, cudaFuncAttributeMaxDynamicSharedMemorySize, TK_SMEM);

    float *score, *hnneg, *px, *Us, *probs;
    int* idxp;
    GETSYM(score, g_score);
    GETSYM(hnneg, g_hnneg); GETSYM(px, g_px); GETSYM(Us, g_Us);
    GETSYM(idxp, g_idx); GETSYM(probs, g_probs);

    bf16 *xh,*xl,*h0h,*h0l,*th,*tl,*lnh,*lnl,*ckh,*ckl;
    bf16 *dh,*dl,*t2h,*t2l,*shp,*slp,*pxh,*pxl,*pth,*ptl;
    GETSYM(xh, g_xh); GETSYM(xl, g_xl);
    GETSYM(h0h, g_h0h); GETSYM(h0l, g_h0l); GETSYM(th, g_th);  GETSYM(tl, g_tl);
    GETSYM(lnh, g_lnh); GETSYM(lnl, g_lnl); GETSYM(ckh, g_ckh); GETSYM(ckl, g_ckl);
    GETSYM(dh, g_dh); GETSYM(dl, g_dl); GETSYM(t2h, g_t2h); GETSYM(t2l, g_t2l);
    GETSYM(shp, g_sh); GETSYM(slp, g_sl);
    GETSYM(pxh, g_pxh); GETSYM(pxl, g_pxl); GETSYM(pth, g_pth); GETSYM(ptl, g_ptl);

    bf16 *winh,*winl,*we1h,*we1l,*we2h,*we2l,*wsh,*wsl,*wt1h,*wt1l,*wt2h,*wt2l,*wp1h,*wp1l,*wp2h,*wp2l;
    GETSYM(winh, g_winh); GETSYM(winl, g_winl);
    GETSYM(we1h, g_we1h); GETSYM(we1l, g_we1l);
    GETSYM(we2h, g_we2h); GETSYM(we2l, g_we2l);
    GETSYM(wsh, g_wsh);   GETSYM(wsl, g_wsl);
    GETSYM(wt1h, g_wt1h); GETSYM(wt1l, g_wt1l);
    GETSYM(wt2h, g_wt2h); GETSYM(wt2l, g_wt2l);
    GETSYM(wp1h, g_wp1h); GETSYM(wp1l, g_wp1l);
    GETSYM(wp2h, g_wp2h); GETSYM(wp2l, g_wp2l);

    // [0..2] prep
    transpose_group3<<<dim3(512, 3), 128>>>(We1, Wt1, Wp1,
                                            we1h, we1l, wt1h, wt1l, wp1h, wp1l);
    transpose_group5<<<dim3(256, 5), 128>>>(W_in, We2, Ws, Wt2, Wp2,
                                            winh, winl, we2h, we2l, wsh, wsl,
                                            wt2h, wt2l, wp2h, wp2l);
    split_x_all<<<4096, 256>>>(cand_x, x_num, xh, xl);

    const int GT = (NT + 127) / 128;     // 790

    // [3..5] combined encode (full 3-segment precision)
    gemm_mma<<<dim3(2, GT), 256, GEMM_SMEM>>>(xh, xl, winh, winl, b_in,
                                              nullptr, nullptr, nullptr,
                                              nullptr, h0h, h0l, NT, 256, 96, 8);
    gemm_mma<<<dim3(4, GT), 256, GEMM_SMEM>>>(h0h, h0l, we1h, we1l, be1,
                                              nullptr, nullptr, nullptr,
                                              nullptr, th, tl, NT, 512, 256, 1 | 8);
    gemm_mma<<<dim3(2, GT), 256, GEMM_SMEM>>>(th, tl, we2h, we2l, be2,
                                              nullptr, h0h, h0l,
                                              nullptr, h0h, h0l, NT, 256, 512, 16 | 8);
    ln_split_warp2<<<(NT + 7) / 8, 256>>>(h0h, h0l, g_m, b_m, lnh, lnl, NT);
    gemm_mma<<<dim3(2, GT), 256, GEMM_SMEM>>>(lnh, lnl, wsh, wsl, bs,
                                              nullptr, nullptr, nullptr,
                                              nullptr, ckh, ckl, NT, 256, 256, 8);
    halfnorm_neg_warp<<<(NCAND + 7) / 8, 256>>>(ckh, ckl, hnneg, NCAND);

    // similarity scores — full precision, swapped raster for L2 reuse
    gemm_mma<<<dim3(8, 782), 256, GEMM_SMEM>>>(
        ckh + (size_t)NCAND * DM, ckl + (size_t)NCAND * DM, ckh, ckl, hnneg,
        nullptr, nullptr, nullptr,
        score, nullptr, nullptr, BQ, NCAND, 256, 4 | 32);

    topk_softmax_kernel<<<BQ, 256, TK_SMEM>>>(score, NCAND, idxp, probs);
    build_d_split_warp<<<(RN + 7) / 8, 256>>>(ckh, ckl, idxp, dh, dl, RN);

    // value MLP stage 1 — 2-segment (post-selection)
    gemm_mma<<<dim3(4, 768), 256, GEMM_SMEM>>>(dh, dl, wt1h, wt1l, nullptr,
                                               nullptr, nullptr, nullptr,
                                               nullptr, t2h, t2l, RN, 512, 256, 1 | 8 | 64);
    // fold prob-weighting BEFORE Wt2 (linearity): S = sum_m p_m T2_m
    weighted_sum_t2<<<BQ, 256>>>(t2h, t2l, probs, shp, slp);
    // tiny GEMM: Us = S @ Wt2^T  (3-segment, cost negligible)
    gemm_mma<<<dim3(2, 8), 256, GEMM_SMEM>>>(shp, slp, wt2h, wt2l, nullptr,
                                             nullptr, nullptr, nullptr,
                                             Us, nullptr, nullptr, BQ, 256, 512, 4);

    combine_kernel<<<BQ, 256>>>(h0h, h0l, Us, probs, idxp, cand_y, Wy, by, bt2,
                                px, pxh, pxl);

    // predictor + head (full precision)
    gemm_mma<<<dim3(4, 8), 256, GEMM_SMEM>>>(pxh, pxl, wp1h, wp1l, bp1,
                                             nullptr, nullptr, nullptr,
                                             nullptr, pth, ptl, BQ, 512, 256, 1 | 8);
    gemm_mma<<<dim3(2, 8), 256, GEMM_SMEM>>>(pth, ptl, wp2h, wp2l, bp2,
                                             px, nullptr, nullptr,
                                             px, nullptr, nullptr, BQ, 256, 512, 2 | 4);
    head_kernel<<<BQ, 256>>>(px, g_h, b_h, Wh, bh, out);

    (void)in_sizes; (void)out_size;
}

// round 16
// speedup vs baseline: 1.5293x; 1.0558x over previous
#include <cuda_runtime.h>
#include <cuda_bf16.h>
#include <math.h>
#include <stdint.h>

// ---------------------------------------------------------------------------
// Problem constants
// ---------------------------------------------------------------------------
#define NCAND 100000
#define BQ    1024
#define NT    (NCAND + BQ)
#define DM    256
#define DH    512
#define NNUM  96
#define MCTX  96
#define RN    (BQ * MCTX)

typedef __nv_bfloat16 bf16;

// ---------------------------------------------------------------------------
// Device scratch
// ---------------------------------------------------------------------------
__device__ float g_score[(size_t)BQ * NCAND];
__device__ float g_hnneg[NCAND];
__device__ float g_px [BQ * DM];
__device__ float g_Us [BQ * DM];
__device__ int   g_idx [BQ * MCTX];
__device__ float g_probs[BQ * MCTX];

__device__ bf16 g_xh [(size_t)NT * 96],  g_xl [(size_t)NT * 96];
__device__ bf16 g_h0h[(size_t)NT * DM],  g_h0l[(size_t)NT * DM];
__device__ bf16 g_th [(size_t)NT * DH],  g_tl [(size_t)NT * DH];
__device__ bf16 g_lnh[(size_t)NT * DM],  g_lnl[(size_t)NT * DM];
__device__ bf16 g_ckh[(size_t)NT * DM],  g_ckl[(size_t)NT * DM];
__device__ bf16 g_dh [(size_t)RN * DM];               // single bf16 now
__device__ bf16 g_t2h[(size_t)RN * DH];               // single bf16 now
__device__ bf16 g_sh [BQ * DH], g_sl [BQ * DH];
__device__ bf16 g_pxh[BQ * DM], g_pxl[BQ * DM];
__device__ bf16 g_pth[BQ * DH], g_ptl[BQ * DH];

__device__ bf16 g_winh[256 * 96],  g_winl[256 * 96];
__device__ bf16 g_we1h[512 * 256], g_we1l[512 * 256];
__device__ bf16 g_we2h[256 * 512], g_we2l[256 * 512];
__device__ bf16 g_wsh [256 * 256], g_wsl [256 * 256];
__device__ bf16 g_wt1h[512 * 256], g_wt1l[512 * 256];
__device__ bf16 g_wt2h[256 * 512], g_wt2l[256 * 512];
__device__ bf16 g_wp1h[512 * 256], g_wp1l[512 * 256];
__device__ bf16 g_wp2h[256 * 512], g_wp2l[256 * 512];

// ---------------------------------------------------------------------------
// Helpers
// ---------------------------------------------------------------------------
__device__ __forceinline__ uint32_t smem_u32(const void* p) {
    uint32_t a;
    asm("{ .reg .u64 t; cvta.to.shared.u64 t, %1; cvt.u32.u64 %0, t; }" : "=r"(a) : "l"(p));
    return a;
}

__device__ __forceinline__ void cp16(uint32_t dst, const void* src, bool valid) {
    int sz = valid ? 16 : 0;
    asm volatile("cp.async.cg.shared.global [%0], [%1], 16, %2;"
                 :: "r"(dst), "l"(src), "r"(sz));
}
#define CP_COMMIT() asm volatile("cp.async.commit_group;")
#define CP_WAIT(n)  asm volatile("cp.async.wait_group %0;" :: "n"(n))

__device__ __forceinline__ void ldsm4(uint32_t addr, uint32_t& r0, uint32_t& r1,
                                      uint32_t& r2, uint32_t& r3) {
    asm volatile("ldmatrix.sync.aligned.m8n8.x4.shared.b16 {%0,%1,%2,%3}, [%4];"
                 : "=r"(r0), "=r"(r1), "=r"(r2), "=r"(r3) : "r"(addr));
}

__device__ __forceinline__ void mma16816(float* c, const uint32_t* a, const uint32_t* b) {
    asm volatile(
        "mma.sync.aligned.m16n8k16.row.col.f32.bf16.bf16.f32 "
        "{%0,%1,%2,%3}, {%4,%5,%6,%7}, {%8,%9}, {%0,%1,%2,%3};"
        : "+f"(c[0]), "+f"(c[1]), "+f"(c[2]), "+f"(c[3])
        : "r"(a[0]), "r"(a[1]), "r"(a[2]), "r"(a[3]), "r"(b[0]), "r"(b[1]));
}

__device__ __forceinline__ float block_sum_256(float v) {
    __shared__ float sh[8];
    int lane = threadIdx.x & 31, w = threadIdx.x >> 5;
    #pragma unroll
    for (int o = 16; o > 0; o >>= 1) v += __shfl_xor_sync(0xffffffffu, v, o);
    __syncthreads();
    if (lane == 0) sh[w] = v;
    __syncthreads();
    float t = sh[0];
    #pragma unroll
    for (int i = 1; i < 8; i++) t += sh[i];
    return t;
}

__device__ __forceinline__ float warp_sum(float v) {
    #pragma unroll
    for (int o = 16; o > 0; o >>= 1) v += __shfl_xor_sync(0xffffffffu, v, o);
    return v;
}

__device__ __forceinline__ void split2(float v, bf16& h, bf16& l) {
    h = __float2bfloat16(v);
    l = __float2bfloat16(v - __bfloat162float(h));
}

// ---------------------------------------------------------------------------
// gemm_mma: FROZEN core (issue -> wait -> barrier -> compute).
// flags: 1 relu, 2 +res(f32), 4 write f32 C, 8 write split (Ch,Cl),
//        16 +res split (Rh+Rl), 32 swap block-index mapping,
//        64 two-segment (AhBh+AlBh), 128 one-segment (AhBh),
//        256 write single bf16 (Ch only)
// ---------------------------------------------------------------------------
#define LDA 40
#define STG_ELEM (128 * LDA)
#define STAGE_BYTES (2 * STG_ELEM * 2)
#define NSTAGE 5
#define GEMM_SMEM (NSTAGE * STAGE_BYTES)

__global__ __launch_bounds__(256, 2)
void gemm_mma(const bf16* __restrict__ Ah, const bf16* __restrict__ Al,
              const bf16* __restrict__ Bh, const bf16* __restrict__ Bl,
              const float* __restrict__ bias, const float* __restrict__ res,
              const bf16* __restrict__ Rh, const bf16* __restrict__ Rl,
              float* __restrict__ C, bf16* __restrict__ Ch, bf16* __restrict__ Cl,
              int M, int N, int Kp, int flags)
{
    extern __shared__ __align__(16) bf16 sdyn[];
    __shared__ float sbias[128];

    const int tid  = threadIdx.x;
    const int lane = tid & 31;
    const int wid  = tid >> 5;
    const int wm   = wid & 3;
    const int wn   = wid >> 2;
    const int bm   = ((flags & 32) ? blockIdx.x : blockIdx.y) * 128;
    const int bn   = ((flags & 32) ? blockIdx.y : blockIdx.x) * 128;

    if (tid < 128) {
        int col = bn + tid;
        sbias[tid] = (bias != nullptr && col < N) ? bias[col] : 0.f;
    }

    const uint32_t sBase = smem_u32(sdyn);

    const bf16* segA[3] = {Ah, Ah, Al};
    const bf16* segB[3] = {Bh, Bl, Bh};
    if (flags & 64) { segA[1] = Al; segB[1] = Bh; }
    int nseg = 3;
    if (flags & 64)  nseg = 2;
    if (flags & 128) nseg = 1;
    const int nk = Kp >> 5;
    const int NC = nseg * nk;

    float acc[2][8][4];
    #pragma unroll
    for (int t = 0; t < 2; t++)
        #pragma unroll
        for (int j = 0; j < 8; j++)
            #pragma unroll
            for (int e = 0; e < 4; e++) acc[t][j][e] = 0.f;

    auto issue = [&](int c, int st) {
        int seg = c / nk;
        int k0  = (c - seg * nk) << 5;
        const bf16* Ap = segA[seg];
        const bf16* Bp = segB[seg];
        uint32_t stA = sBase + (uint32_t)(st * STAGE_BYTES);
        uint32_t stB = stA + STG_ELEM * 2;
        #pragma unroll
        for (int h = 0; h < 2; h++) {
            int q   = tid + h * 256;
            int row = q >> 2;
            int sg  = q & 3;
            uint32_t off = (uint32_t)(row * 80 + sg * 16);
            int ar = bm + row; bool av = ar < M; if (!av) ar = 0;
            cp16(stA + off, Ap + (size_t)ar * Kp + k0 + sg * 8, av);
            int br = bn + row; bool bv = br < N; if (!bv) br = 0;
            cp16(stB + off, Bp + (size_t)br * Kp + k0 + sg * 8, bv);
        }
        CP_COMMIT();
    };

    issue(0, 0);
    issue(1, 1);
    issue(2, 2);
    int st_w = 3, st_r = 0;
    for (int c = 0; c < NC; ++c) {
        if (c + 3 < NC) {
            issue(c + 3, st_w);
            if (++st_w == NSTAGE) st_w = 0;
        } else {
            CP_COMMIT();
        }
        CP_WAIT(3);
        __syncthreads();

        uint32_t stA = sBase + (uint32_t)(st_r * STAGE_BYTES);
        uint32_t stB = stA + STG_ELEM * 2;
        if (++st_r == NSTAGE) st_r = 0;
        uint32_t aBase = stA + (uint32_t)((wm * 32) * 80);
        uint32_t bBase = stB + (uint32_t)((wn * 64) * 80);

        #pragma unroll
        for (int ks = 0; ks < 32; ks += 16) {
            uint32_t a[2][4];
            #pragma unroll
            for (int t = 0; t < 2; t++) {
                uint32_t addr = aBase + (uint32_t)((t * 16 + (lane & 15)) * 80
                                                   + (ks + (lane >> 4) * 8) * 2);
                ldsm4(addr, a[t][0], a[t][1], a[t][2], a[t][3]);
            }
            uint32_t b[8][2];
            #pragma unroll
            for (int jp = 0; jp < 4; jp++) {
                int grp = lane >> 3;
                int row = jp * 16 + (grp >> 1) * 8 + (lane & 7);
                int kof = (grp & 1) * 8;
                uint32_t addr = bBase + (uint32_t)(row * 80 + (ks + kof) * 2);
                ldsm4(addr, b[2 * jp][0], b[2 * jp][1], b[2 * jp + 1][0], b[2 * jp + 1][1]);
            }
            #pragma unroll
            for (int t = 0; t < 2; t++)
                #pragma unroll
                for (int j = 0; j < 8; j++)
                    mma16816(acc[t][j], a[t], b[j]);
        }
    }

    // ---- epilogue ----
    int colb = (lane & 3) * 2;
    #pragma unroll
    for (int t = 0; t < 2; t++) {
        int row0 = bm + wm * 32 + t * 16 + (lane >> 2);
        #pragma unroll
        for (int j = 0; j < 8; j++) {
            int col = bn + wn * 64 + j * 8 + colb;
            if (col >= N) continue;
            #pragma unroll
            for (int half = 0; half < 2; half++) {
                int rr = row0 + half * 8;
                if (rr >= M) continue;
                float v0 = acc[t][j][half * 2 + 0];
                float v1 = acc[t][j][half * 2 + 1];
                int cl = col - bn;
                v0 += sbias[cl]; v1 += sbias[cl + 1];
                if (flags & 1) { v0 = fmaxf(v0, 0.f); v1 = fmaxf(v1, 0.f); }
                size_t o = (size_t)rr * N + col;
                if (flags & 2) {
                    float2 r2 = *reinterpret_cast<const float2*>(res + o);
                    v0 += r2.x; v1 += r2.y;
                }
                if (flags & 16) {
                    __nv_bfloat162 rh = *reinterpret_cast<const __nv_bfloat162*>(Rh + o);
                    __nv_bfloat162 rl = *reinterpret_cast<const __nv_bfloat162*>(Rl + o);
                    v0 += __bfloat162float(rh.x) + __bfloat162float(rl.x);
                    v1 += __bfloat162float(rh.y) + __bfloat162float(rl.y);
                }
                if (flags & 4) {
                    *reinterpret_cast<float2*>(C + o) = make_float2(v0, v1);
                }
                if (flags & 8) {
                    bf16 h0, l0, h1, l1;
                    split2(v0, h0, l0); split2(v1, h1, l1);
                    *reinterpret_cast<__nv_bfloat162*>(Ch + o) = __nv_bfloat162(h0, h1);
                    *reinterpret_cast<__nv_bfloat162*>(Cl + o) = __nv_bfloat162(l0, l1);
                }
                if (flags & 256) {
                    *reinterpret_cast<__nv_bfloat162*>(Ch + o) =
                        __nv_bfloat162(__float2bfloat16(v0), __float2bfloat16(v1));
                }
            }
        }
    }
}

// ---------------------------------------------------------------------------
// Grouped weight prep
// ---------------------------------------------------------------------------
__global__ void transpose_group3(const float* __restrict__ W0, const float* __restrict__ W1,
                                 const float* __restrict__ W2,
                                 bf16* __restrict__ T0h, bf16* __restrict__ T0l,
                                 bf16* __restrict__ T1h, bf16* __restrict__ T1l,
                                 bf16* __restrict__ T2h, bf16* __restrict__ T2l)
{
    int w = blockIdx.y;
    const float* W = (w == 0) ? W0 : (w == 1) ? W1 : W2;
    bf16* Th = (w == 0) ? T0h : (w == 1) ? T1h : T2h;
    bf16* Tl = (w == 0) ? T0l : (w == 1) ? T1l : T2l;
    int n = blockIdx.x;
    for (int k = threadIdx.x; k < 256; k += 128) {
        float v = W[(size_t)k * 512 + n];
        bf16 h, l; split2(v, h, l);
        Th[(size_t)n * 256 + k] = h;
        Tl[(size_t)n * 256 + k] = l;
    }
}

__global__ void transpose_group5(const float* __restrict__ Win, const float* __restrict__ We2,
                                 const float* __restrict__ Ws,  const float* __restrict__ Wt2,
                                 const float* __restrict__ Wp2,
                                 bf16* __restrict__ T0h, bf16* __restrict__ T0l,
                                 bf16* __restrict__ T1h, bf16* __restrict__ T1l,
                                 bf16* __restrict__ T2h, bf16* __restrict__ T2l,
                                 bf16* __restrict__ T3h, bf16* __restrict__ T3l,
                                 bf16* __restrict__ T4h, bf16* __restrict__ T4l)
{
    int w = blockIdx.y;
    const float* Wt[5] = {Win, We2, Ws, Wt2, Wp2};
    bf16* Tht[5] = {T0h, T1h, T2h, T3h, T4h};
    bf16* Tlt[5] = {T0l, T1l, T2l, T3l, T4l};
    const int Ks [5] = {96, 512, 256, 512, 512};
    const int Kps[5] = {96, 512, 256, 512, 512};
    const float* W = Wt[w];
    bf16* Th = Tht[w];
    bf16* Tl = Tlt[w];
    int K = Ks[w], Kp = Kps[w];
    int n = blockIdx.x;
    for (int k = threadIdx.x; k < Kp; k += 128) {
        float v = (k < K) ? W[(size_t)k * 256 + n] : 0.f;
        bf16 h, l; split2(v, h, l);
        Th[(size_t)n * Kp + k] = h;
        Tl[(size_t)n * Kp + k] = l;
    }
}

__global__ __launch_bounds__(256)
void split_x_all(const float* __restrict__ cand, const float* __restrict__ q,
                 bf16* __restrict__ Xh, bf16* __restrict__ Xl)
{
    size_t total = (size_t)NT * NNUM;
    for (size_t e = (size_t)blockIdx.x * 256 + threadIdx.x; e < total;
         e += (size_t)gridDim.x * 256) {
        size_t r = e / NNUM;
        int t = (int)(e - r * NNUM);
        float v = (r < NCAND) ? cand[r * NNUM + t] : q[(r - NCAND) * NNUM + t];
        bf16 h, l; split2(v, h, l);
        Xh[e] = h;
        Xl[e] = l;
    }
}

// ---------------------------------------------------------------------------
// Warp-per-row LayerNorm from SPLIT input -> split output ; warp half-norm
// ---------------------------------------------------------------------------
__global__ __launch_bounds__(256)
void ln_split_warp2(const bf16* __restrict__ Hh, const bf16* __restrict__ Hl,
                    const float* __restrict__ g, const float* __restrict__ b,
                    bf16* __restrict__ Yh, bf16* __restrict__ Yl, int nrows)
{
    int row = blockIdx.x * 8 + (threadIdx.x >> 5);
    int lane = threadIdx.x & 31;
    if (row >= nrows) return;
    uint4 uh = *reinterpret_cast<const uint4*>(Hh + (size_t)row * DM + lane * 8);
    uint4 ul = *reinterpret_cast<const uint4*>(Hl + (size_t)row * DM + lane * 8);
    const bf16* ph = reinterpret_cast<const bf16*>(&uh);
    const bf16* pl = reinterpret_cast<const bf16*>(&ul);
    float fv[8];
    float s = 0.f;
    #pragma unroll
    for (int i = 0; i < 8; i++) {
        fv[i] = __bfloat162float(ph[i]) + __bfloat162float(pl[i]);
        s += fv[i];
    }
    float mu = warp_sum(s) * (1.f / DM);
    float vs = 0.f;
    #pragma unroll
    for (int i = 0; i < 8; i++) { fv[i] -= mu; vs += fv[i] * fv[i]; }
    float rstd = rsqrtf(warp_sum(vs) * (1.f / DM) + 1e-5f);
    float4 g0 = *reinterpret_cast<const float4*>(g + lane * 8);
    float4 g1 = *reinterpret_cast<const float4*>(g + lane * 8 + 4);
    float4 b0 = *reinterpret_cast<const float4*>(b + lane * 8);
    float4 b1 = *reinterpret_cast<const float4*>(b + lane * 8 + 4);
    float gr[8] = {g0.x, g0.y, g0.z, g0.w, g1.x, g1.y, g1.z, g1.w};
    float br[8] = {b0.x, b0.y, b0.z, b0.w, b1.x, b1.y, b1.z, b1.w};
    bf16 hv[8], lv[8];
    #pragma unroll
    for (int i = 0; i < 8; i++) {
        float y = fv[i] * rstd * gr[i] + br[i];
        split2(y, hv[i], lv[i]);
    }
    *reinterpret_cast<uint4*>(Yh + (size_t)row * DM + lane * 8) = *reinterpret_cast<uint4*>(hv);
    *reinterpret_cast<uint4*>(Yl + (size_t)row * DM + lane * 8) = *reinterpret_cast<uint4*>(lv);
}

__global__ __launch_bounds__(256)
void halfnorm_neg_warp(const bf16* __restrict__ Kh, const bf16* __restrict__ Kl,
                       float* __restrict__ hn, int nrows)
{
    int row = blockIdx.x * 8 + (threadIdx.x >> 5);
    int lane = threadIdx.x & 31;
    if (row >= nrows) return;
    uint4 uh = *reinterpret_cast<const uint4*>(Kh + (size_t)row * DM + lane * 8);
    uint4 ul = *reinterpret_cast<const uint4*>(Kl + (size_t)row * DM + lane * 8);
    const bf16* ph = reinterpret_cast<const bf16*>(&uh);
    const bf16* pl = reinterpret_cast<const bf16*>(&ul);
    float s = 0.f;
    #pragma unroll
    for (int i = 0; i < 8; i++) {
        float v = __bfloat162float(ph[i]) + __bfloat162float(pl[i]);
        s += v * v;
    }
    float tot = warp_sum(s);
    if (lane == 0) hn[row] = -0.5f * tot;
}

// ---------------------------------------------------------------------------
// Top-96 + softmax: two-scan compaction with fallback (proven).
// ---------------------------------------------------------------------------
#define TKCAP 4096
#define TK_SMEM 81920

__device__ __forceinline__ unsigned f2o(float f) {
    unsigned u = __float_as_uint(f);
    return (u & 0x80000000u) ? ~u : (u | 0x80000000u);
}

__global__ __launch_bounds__(256)
void topk_softmax_kernel(const float* __restrict__ score, int N,
                         int* __restrict__ out_idx, float* __restrict__ out_probs)
{
    extern __shared__ unsigned char tks[];
    unsigned* hist = (unsigned*)tks;
    float* v0 = (float*)(tks + 16384);
    int*   i0 = (int*)  (tks + 32768);
    float* v1 = (float*)(tks + 49152);
    int*   i1 = (int*)  (tks + 65536);

    int row = blockIdx.x;
    const float* s = score + (size_t)row * N;
    int tid = threadIdx.x;
    int lane = tid & 31;
    int N4 = N >> 2;

    __shared__ float tvals[MCTX];
    __shared__ int   tinds[MCTX];
    __shared__ int cnt_top, cnt_c, cnt_c2, cnt_eq;
    __shared__ unsigned sh_sel;
    __shared__ int sh_krem;
    __shared__ float s_max, s_sum;
    __shared__ float evals[MCTX];

    for (int b = tid; b < 4096; b += 256) hist[b] = 0;
    if (tid == 0) { cnt_top = 0; cnt_c = 0; cnt_c2 = 0; cnt_eq = 0; }
    __syncthreads();
    for (int j4 = tid; j4 < N4; j4 += 256) {
        float4 f4 = *reinterpret_cast<const float4*>(s + j4 * 4);
        atomicAdd(&hist[f2o(f4.x) >> 20], 1u);
        atomicAdd(&hist[f2o(f4.y) >> 20], 1u);
        atomicAdd(&hist[f2o(f4.z) >> 20], 1u);
        atomicAdd(&hist[f2o(f4.w) >> 20], 1u);
    }
    __syncthreads();
    if (tid == 0) {
        int cum = 0;
        unsigned bsel = 0;
        for (int b = 4095; b >= 0; b--) {
            int c = (int)hist[b];
            if (cum + c >= MCTX) { bsel = (unsigned)b; break; }
            cum += c;
        }
        sh_sel = bsel;
        sh_krem = MCTX - cum;
    }
    __syncthreads();
    unsigned sel = sh_sel;

    for (int j4 = tid; j4 < N4; j4 += 256) {
        float4 f4 = *reinterpret_cast<const float4*>(s + j4 * 4);
        float fa[4] = {f4.x, f4.y, f4.z, f4.w};
        #pragma unroll
        for (int e = 0; e < 4; e++) {
            float f = fa[e];
            unsigned b = f2o(f) >> 20;
            if (b > sel) {
                int p = atomicAdd(&cnt_top, 1);
                tvals[p] = f; tinds[p] = j4 * 4 + e;
            } else if (b == sel) {
                int p = atomicAdd(&cnt_c, 1);
                if (p < TKCAP) { v0[p] = f; i0[p] = j4 * 4 + e; }
            }
        }
    }
    __syncthreads();

    if (cnt_c <= TKCAP) {
        int nc = cnt_c;
        int krem = sh_krem;
        for (int b = tid; b < 4096; b += 256) hist[b] = 0;
        __syncthreads();
        for (int t = tid; t < nc; t += 256)
            atomicAdd(&hist[(f2o(v0[t]) >> 8) & 0xFFFu], 1);
        __syncthreads();
        if (tid == 0) {
            int cum = 0;
            unsigned bsel = 0;
            for (int b = 4095; b >= 0; b--) {
                int c = (int)hist[b];
                if (cum + c >= krem) { bsel = (unsigned)b; break; }
                cum += c;
            }
            sh_sel = bsel;
            sh_krem = krem - cum;
        }
        __syncthreads();
        unsigned sel2 = sh_sel;
        for (int t = tid; t < nc; t += 256) {
            float f = v0[t];
            unsigned m = (f2o(f) >> 8) & 0xFFFu;
            if (m > sel2) {
                int p = atomicAdd(&cnt_top, 1);
                tvals[p] = f; tinds[p] = i0[t];
            } else if (m == sel2) {
                int p = atomicAdd(&cnt_c2, 1);
                v1[p] = f; i1[p] = i0[t];
            }
        }
        __syncthreads();

        int nc2 = cnt_c2;
        int krem2 = sh_krem;
        for (int b = tid; b < 256; b += 256) hist[b] = 0;
        __syncthreads();
        for (int t = tid; t < nc2; t += 256)
            atomicAdd(&hist[f2o(v1[t]) & 0xFFu], 1);
        __syncthreads();
        if (tid == 0) {
            int cum = 0;
            unsigned bsel = 0;
            for (int b = 255; b >= 0; b--) {
                int c = (int)hist[b];
                if (cum + c >= krem2) { bsel = (unsigned)b; break; }
                cum += c;
            }
            sh_sel = bsel;
            sh_krem = krem2 - cum;
        }
        __syncthreads();
        unsigned sel3 = sh_sel;
        int need = sh_krem;
        for (int t = tid; t < nc2; t += 256) {
            float f = v1[t];
            unsigned lo = f2o(f) & 0xFFu;
            if (lo > sel3) {
                int p = atomicAdd(&cnt_top, 1);
                tvals[p] = f; tinds[p] = i1[t];
            } else if (lo == sel3) {
                int p = atomicAdd(&cnt_eq, 1);
                if (p < need) {
                    int q = atomicAdd(&cnt_top, 1);
                    tvals[q] = f; tinds[q] = i1[t];
                }
            }
        }
        __syncthreads();
    } else {
        __syncthreads();
        if (tid == 0) { cnt_top = 0; cnt_eq = 0; sh_sel = 0u; sh_krem = MCTX; }
        __syncthreads();
        int nIter = (N + 255) / 256;
        for (int shift = 24; shift >= 0; shift -= 8) {
            for (int b = tid; b < 256; b += 256) hist[b] = 0;
            __syncthreads();
            unsigned prefix = sh_sel;
            unsigned mask_hi = (shift == 24) ? 0u : (0xFFFFFFFFu << (shift + 8));
            for (int it = 0; it < nIter; it++) {
                int j = it * 256 + tid;
                bool act = false;
                unsigned bin = 0;
                if (j < N) {
                    unsigned u = f2o(s[j]);
                    act = ((u & mask_hi) == prefix);
                    bin = (u >> shift) & 255u;
                }
                int key = act ? (int)bin : (256 + lane);
                unsigned peers = __match_any_sync(0xffffffffu, key);
                int leader = __ffs(peers) - 1;
                if (act && lane == leader) atomicAdd(&hist[bin], __popc(peers));
            }
            __syncthreads();
            if (tid == 0) {
                int kr = sh_krem;
                int cum = 0, bsel = 0;
                for (int bb = 255; bb >= 0; bb--) {
                    int c = (int)hist[bb];
                    if (cum + c >= kr) { bsel = bb; break; }
                    cum += c;
                }
                sh_sel = prefix | ((unsigned)bsel << shift);
                sh_krem = kr - cum;
            }
            __syncthreads();
        }
        unsigned T = sh_sel;
        int need = sh_krem;
        for (int j = tid; j < N; j += 256) {
            float f = s[j];
            unsigned u = f2o(f);
            if (u > T) {
                int p = atomicAdd(&cnt_top, 1);
                tvals[p] = f; tinds[p] = j;
            } else if (u == T) {
                int p = atomicAdd(&cnt_eq, 1);
                if (p < need) {
                    int q = atomicAdd(&cnt_top, 1);
                    tvals[q] = f; tinds[q] = j;
                }
            }
        }
        __syncthreads();
    }

    if (tid == 0) {
        float mx = -1e30f;
        for (int m = 0; m < MCTX; m++) mx = fmaxf(mx, 2.f * tvals[m]);
        s_max = mx;
    }
    __syncthreads();
    if (tid < MCTX) evals[tid] = expf(2.f * tvals[tid] - s_max);
    __syncthreads();
    if (tid == 0) {
        float sm = 0.f;
        for (int m = 0; m < MCTX; m++) sm += evals[m];
        s_sum = sm;
    }
    __syncthreads();
    if (tid < MCTX) {
        out_probs[row * MCTX + tid] = evals[tid] / s_sum;
        out_idx[row * MCTX + tid]   = tinds[tid];
    }
}

// ---------------------------------------------------------------------------
// Warp-per-row D build: SINGLE bf16 output (value path tolerates rounding)
// ---------------------------------------------------------------------------
__global__ __launch_bounds__(256)
void build_d_single_warp(const bf16* __restrict__ Kh, const bf16* __restrict__ Kl,
                         const int* __restrict__ idx,
                         bf16* __restrict__ Dh, int nrows)
{
    int r = blockIdx.x * 8 + (threadIdx.x >> 5);
    int lane = threadIdx.x & 31;
    if (r >= nrows) return;
    int b = r / MCTX;
    int j = idx[r];
    size_t oq = (size_t)(NCAND + b) * DM + lane * 8;
    size_t oc = (size_t)j * DM + lane * 8;
    uint4 qh = *reinterpret_cast<const uint4*>(Kh + oq);
    uint4 ql = *reinterpret_cast<const uint4*>(Kl + oq);
    uint4 ch = *reinterpret_cast<const uint4*>(Kh + oc);
    uint4 cl = *reinterpret_cast<const uint4*>(Kl + oc);
    const bf16* pqh = reinterpret_cast<const bf16*>(&qh);
    const bf16* pql = reinterpret_cast<const bf16*>(&ql);
    const bf16* pch = reinterpret_cast<const bf16*>(&ch);
    const bf16* pcl = reinterpret_cast<const bf16*>(&cl);
    bf16 hv[8];
    #pragma unroll
    for (int i = 0; i < 8; i++) {
        float kq = __bfloat162float(pqh[i]) + __bfloat162float(pql[i]);
        float kc = __bfloat162float(pch[i]) + __bfloat162float(pcl[i]);
        hv[i] = __float2bfloat16(kq - kc);
    }
    *reinterpret_cast<uint4*>(Dh + (size_t)r * DM + lane * 8) = *reinterpret_cast<uint4*>(hv);
}

// ---------------------------------------------------------------------------
// Weighted sum over contexts: S_b = sum_m p[b,m] * T2[b*96+m, :]
// T2 single bf16; bf162 coalesced loads; split output for the tiny 3-seg GEMM.
// ---------------------------------------------------------------------------
__global__ __launch_bounds__(256)
void weighted_sum_t2(const bf16* __restrict__ T2h,
                     const float* __restrict__ probs,
                     bf16* __restrict__ Sh, bf16* __restrict__ Sl)
{
    int b = blockIdx.x;
    int tid = threadIdx.x;
    __shared__ float p_s[MCTX];
    if (tid < MCTX) p_s[tid] = probs[b * MCTX + tid];
    __syncthreads();
    float acc0 = 0.f, acc1 = 0.f;
    const size_t base = (size_t)b * MCTX * DH;
    #pragma unroll 4
    for (int m = 0; m < MCTX; m++) {
        __nv_bfloat162 t2 = *reinterpret_cast<const __nv_bfloat162*>(
            T2h + base + (size_t)m * DH + 2 * tid);
        float p = p_s[m];
        acc0 += p * __bfloat162float(t2.x);
        acc1 += p * __bfloat162float(t2.y);
    }
    bf16 h0, l0, h1, l1;
    split2(acc0, h0, l0);
    split2(acc1, h1, l1);
    size_t o = (size_t)b * DH + 2 * tid;
    *reinterpret_cast<__nv_bfloat162*>(Sh + o) = __nv_bfloat162(h0, h1);
    *reinterpret_cast<__nv_bfloat162*>(Sl + o) = __nv_bfloat162(l0, l1);
}

// ---------------------------------------------------------------------------
// Combine: x = h + Us + ybar*Wy + by + bt2
// ---------------------------------------------------------------------------
__global__ __launch_bounds__(256)
void combine_kernel(const bf16* __restrict__ Hh, const bf16* __restrict__ Hl,
                    const float* __restrict__ Us,
                    const float* __restrict__ probs, const int* __restrict__ idx,
                    const float* __restrict__ cand_y, const float* __restrict__ Wy,
                    const float* __restrict__ by, const float* __restrict__ bt2,
                    float* __restrict__ xout, bf16* __restrict__ Xh, bf16* __restrict__ Xl)
{
    int b = blockIdx.x;
    int tid = threadIdx.x;
    __shared__ float py_s[MCTX];
    __shared__ float ybar_s;
    if (tid < MCTX)
        py_s[tid] = probs[b * MCTX + tid] * cand_y[idx[b * MCTX + tid]];
    __syncthreads();
    if (tid == 0) {
        float yb = 0.f;
        for (int m = 0; m < MCTX; m++) yb += py_s[m];
        ybar_s = yb;
    }
    __syncthreads();
    size_t ho = (size_t)(NCAND + b) * DM + tid;
    float hres = __bfloat162float(Hh[ho]) + __bfloat162float(Hl[ho]);
    float v = hres + Us[b * DM + tid] + ybar_s * Wy[tid] + by[tid] + bt2[tid];
    xout[b * DM + tid] = v;
    bf16 hh, ll; split2(v, hh, ll);
    Xh[b * DM + tid] = hh;
    Xl[b * DM + tid] = ll;
}

// ---------------------------------------------------------------------------
// Head
// ---------------------------------------------------------------------------
__global__ __launch_bounds__(256)
void head_kernel(const float* __restrict__ X, const float* __restrict__ g,
                 const float* __restrict__ b, const float* __restrict__ Wh,
                 const float* __restrict__ bh, float* __restrict__ out)
{
    int r = blockIdx.x;
    int tid = threadIdx.x;
    float x = X[(size_t)r * DM + tid];
    float mu = block_sum_256(x) * (1.f / DM);
    float d = x - mu;
    float var = block_sum_256(d * d) * (1.f / DM);
    float y = d * rsqrtf(var + 1e-5f) * g[tid] + b[tid];
    float t = fmaxf(y, 0.f) * Wh[tid];
    float tot = block_sum_256(t);
    if (tid == 0) out[r] = tot + bh[0];
}

// ---------------------------------------------------------------------------
// Launcher
// ---------------------------------------------------------------------------
#define GETSYM(var, sym) cudaGetSymbolAddress((void**)&(var), sym)

extern "C" void kernel_launch(void* const* d_in, const int* in_sizes, int n_in,
                              void* d_out, int out_size)
{
    const float* x_num  = (const float*)d_in[0];
    const float* cand_x = (const float*)d_in[1];
    const float* cand_y = (const float*)d_in[2];
    int off = (n_in >= 27) ? 1 : 0;
    int i = 3 + off;
    const float* W_in = (const float*)d_in[i++]; const float* b_in = (const float*)d_in[i++];
    const float* We1  = (const float*)d_in[i++]; const float* be1  = (const float*)d_in[i++];
    const float* We2  = (const float*)d_in[i++]; const float* be2  = (const float*)d_in[i++];
    const float* g_m  = (const float*)d_in[i++]; const float* b_m  = (const float*)d_in[i++];
    const float* Ws   = (const float*)d_in[i++]; const float* bs   = (const float*)d_in[i++];
    const float* Wy   = (const float*)d_in[i++]; const float* by   = (const float*)d_in[i++];
    const float* Wt1  = (const float*)d_in[i++];
    const float* Wt2  = (const float*)d_in[i++]; const float* bt2  = (const float*)d_in[i++];
    const float* Wp1  = (const float*)d_in[i++]; const float* bp1  = (const float*)d_in[i++];
    const float* Wp2  = (const float*)d_in[i++]; const float* bp2  = (const float*)d_in[i++];
    const float* g_h  = (const float*)d_in[i++]; const float* b_h  = (const float*)d_in[i++];
    const float* Wh   = (const float*)d_in[i++]; const float* bh   = (const float*)d_in[i++];
    float* out = (float*)d_out;

    cudaFuncSetAttribute(gemm_mma, cudaFuncAttributeMaxDynamicSharedMemorySize, GEMM_SMEM);
    cudaFuncSetAttribute(topk_softmax_kernel, cudaFuncAttributeMaxDynamicSharedMemorySize, TK_SMEM);

    float *score, *hnneg, *px, *Us, *probs;
    int* idxp;
    GETSYM(score, g_score);
    GETSYM(hnneg, g_hnneg); GETSYM(px, g_px); GETSYM(Us, g_Us);
    GETSYM(idxp, g_idx); GETSYM(probs, g_probs);

    bf16 *xh,*xl,*h0h,*h0l,*th,*tl,*lnh,*lnl,*ckh,*ckl;
    bf16 *dh,*t2h,*shp,*slp,*pxh,*pxl,*pth,*ptl;
    GETSYM(xh, g_xh); GETSYM(xl, g_xl);
    GETSYM(h0h, g_h0h); GETSYM(h0l, g_h0l); GETSYM(th, g_th);  GETSYM(tl, g_tl);
    GETSYM(lnh, g_lnh); GETSYM(lnl, g_lnl); GETSYM(ckh, g_ckh); GETSYM(ckl, g_ckl);
    GETSYM(dh, g_dh); GETSYM(t2h, g_t2h);
    GETSYM(shp, g_sh); GETSYM(slp, g_sl);
    GETSYM(pxh, g_pxh); GETSYM(pxl, g_pxl); GETSYM(pth, g_pth); GETSYM(ptl, g_ptl);

    bf16 *winh,*winl,*we1h,*we1l,*we2h,*we2l,*wsh,*wsl,*wt1h,*wt1l,*wt2h,*wt2l,*wp1h,*wp1l,*wp2h,*wp2l;
    GETSYM(winh, g_winh); GETSYM(winl, g_winl);
    GETSYM(we1h, g_we1h); GETSYM(we1l, g_we1l);
    GETSYM(we2h, g_we2h); GETSYM(we2l, g_we2l);
    GETSYM(wsh, g_wsh);   GETSYM(wsl, g_wsl);
    GETSYM(wt1h, g_wt1h); GETSYM(wt1l, g_wt1l);
    GETSYM(wt2h, g_wt2h); GETSYM(wt2l, g_wt2l);
    GETSYM(wp1h, g_wp1h); GETSYM(wp1l, g_wp1l);
    GETSYM(wp2h, g_wp2h); GETSYM(wp2l, g_wp2l);

    // [0..2] prep
    transpose_group3<<<dim3(512, 3), 128>>>(We1, Wt1, Wp1,
                                            we1h, we1l, wt1h, wt1l, wp1h, wp1l);
    transpose_group5<<<dim3(256, 5), 128>>>(W_in, We2, Ws, Wt2, Wp2,
                                            winh, winl, we2h, we2l, wsh, wsl,
                                            wt2h, wt2l, wp2h, wp2l);
    split_x_all<<<4096, 256>>>(cand_x, x_num, xh, xl);

    const int GT = (NT + 127) / 128;     // 790

    // [3..5] combined encode (full 3-segment precision)
    gemm_mma<<<dim3(2, GT), 256, GEMM_SMEM>>>(xh, xl, winh, winl, b_in,
                                              nullptr, nullptr, nullptr,
                                              nullptr, h0h, h0l, NT, 256, 96, 8);
    gemm_mma<<<dim3(4, GT), 256, GEMM_SMEM>>>(h0h, h0l, we1h, we1l, be1,
                                              nullptr, nullptr, nullptr,
                                              nullptr, th, tl, NT, 512, 256, 1 | 8);
    gemm_mma<<<dim3(2, GT), 256, GEMM_SMEM>>>(th, tl, we2h, we2l, be2,
                                              nullptr, h0h, h0l,
                                              nullptr, h0h, h0l, NT, 256, 512, 16 | 8);
    ln_split_warp2<<<(NT + 7) / 8, 256>>>(h0h, h0l, g_m, b_m, lnh, lnl, NT);
    gemm_mma<<<dim3(2, GT), 256, GEMM_SMEM>>>(lnh, lnl, wsh, wsl, bs,
                                              nullptr, nullptr, nullptr,
                                              nullptr, ckh, ckl, NT, 256, 256, 8);
    halfnorm_neg_warp<<<(NCAND + 7) / 8, 256>>>(ckh, ckl, hnneg, NCAND);

    // similarity scores — full precision, swapped raster for L2 reuse
    gemm_mma<<<dim3(8, 782), 256, GEMM_SMEM>>>(
        ckh + (size_t)NCAND * DM, ckl + (size_t)NCAND * DM, ckh, ckl, hnneg,
        nullptr, nullptr, nullptr,
        score, nullptr, nullptr, BQ, NCAND, 256, 4 | 32);

    topk_softmax_kernel<<<BQ, 256, TK_SMEM>>>(score, NCAND, idxp, probs);
    build_d_single_warp<<<(RN + 7) / 8, 256>>>(ckh, ckl, idxp, dh, RN);

    // value MLP stage 1 — ONE segment (D single bf16), T2 single bf16 out
    gemm_mma<<<dim3(4, 768), 256, GEMM_SMEM>>>(dh, dh, wt1h, wt1h, nullptr,
                                               nullptr, nullptr, nullptr,
                                               nullptr, t2h, nullptr,
                                               RN, 512, 256, 1 | 128 | 256);
    // fold prob-weighting BEFORE Wt2 (linearity)
    weighted_sum_t2<<<BQ, 256>>>(t2h, probs, shp, slp);
    // tiny GEMM: Us = S @ Wt2^T  (3-segment)
    gemm_mma<<<dim3(2, 8), 256, GEMM_SMEM>>>(shp, slp, wt2h, wt2l, nullptr,
                                             nullptr, nullptr, nullptr,
                                             Us, nullptr, nullptr, BQ, 256, 512, 4);

    combine_kernel<<<BQ, 256>>>(h0h, h0l, Us, probs, idxp, cand_y, Wy, by, bt2,
                                px, pxh, pxl);

    // predictor + head (full precision)
    gemm_mma<<<dim3(4, 8), 256, GEMM_SMEM>>>(pxh, pxl, wp1h, wp1l, bp1,
                                             nullptr, nullptr, nullptr,
                                             nullptr, pth, ptl, BQ, 512, 256, 1 | 8);
    gemm_mma<<<dim3(2, 8), 256, GEMM_SMEM>>>(pth, ptl, wp2h, wp2l, bp2,
                                             px, nullptr, nullptr,
                                             px, nullptr, nullptr, BQ, 256, 512, 2 | 4);
    head_kernel<<<BQ, 256>>>(px, g_h, b_h, Wh, bh, out);

    (void)in_sizes; (void)out_size;
}